// round 1
// baseline (speedup 1.0000x reference)
#include <cuda_runtime.h>

#define NN 50000
#define NE 600000
#define NR 16
#define NG 128

// ---------------- scratch (static device globals; no allocation) ----------------
__device__ float g_T[(size_t)NR * NN * 256];   // per-relation transformed nodes (worst case dout=256)
__device__ float g_hA[(size_t)NN * 256];
__device__ float g_hB[(size_t)NN * 256];
__device__ int   g_deg[NN];
__device__ int   g_rowptr[NN + 1];
__device__ int   g_fill[NN];
__device__ int   g_esrc[NE];
__device__ int   g_erel[NE];
__device__ float g_pool[NG * 128];
__device__ float g_cnt[NG];
__device__ float g_hgA[NG * 256];
__device__ float g_hgB[NG * 256];

// ---------------- small utility kernels ----------------
__global__ void k_init() {
    int i = blockIdx.x * blockDim.x + threadIdx.x;
    if (i < NN) g_deg[i] = 0;
    if (i < NG * 128) g_pool[i] = 0.f;
    if (i < NG) g_cnt[i] = 0.f;
}

__global__ void k_hist(const int* __restrict__ dst) {
    int e = blockIdx.x * blockDim.x + threadIdx.x;
    if (e < NE) atomicAdd(&g_deg[dst[e]], 1);
}

// single-block exclusive scan of g_deg -> g_rowptr (and g_fill copy)
__global__ void k_scan() {
    __shared__ int s[1024];
    int t = threadIdx.x;
    const int CH = (NN + 1023) / 1024;  // 49
    int beg = t * CH;
    int end = beg + CH; if (end > NN) end = NN;
    int sum = 0;
    for (int i = beg; i < end && i < NN; i++) sum += g_deg[i];
    s[t] = sum;
    __syncthreads();
    for (int off = 1; off < 1024; off <<= 1) {
        int v = (t >= off) ? s[t - off] : 0;
        __syncthreads();
        s[t] += v;
        __syncthreads();
    }
    int run = (t == 0) ? 0 : s[t - 1];
    for (int i = beg; i < end && i < NN; i++) {
        g_rowptr[i] = run;
        g_fill[i] = run;
        run += g_deg[i];
    }
    if (t == 1023) g_rowptr[NN] = run;
}

__global__ void k_scatter(const int* __restrict__ src, const int* __restrict__ dst,
                          const int* __restrict__ rel) {
    int e = blockIdx.x * blockDim.x + threadIdx.x;
    if (e < NE) {
        int p = atomicAdd(&g_fill[dst[e]], 1);
        g_esrc[p] = src[e];
        g_erel[p] = rel[e];
    }
}

// ---------------- fp32 tiled GEMM: C[z] = A @ B[z] (+bias, optional relu) ----------------
// A: [M,K] row-major (shared across batch). B: [K,Nc] row-major, batch stride strideB.
// C: [M,Nc] row-major, batch stride strideC. Requires K%8==0, Nc%128==0.
__global__ void __launch_bounds__(256) k_gemm(
    const float* __restrict__ A, const float* __restrict__ B,
    const float* __restrict__ bias, float* __restrict__ C,
    int M, int K, int Nc, size_t strideB, size_t strideC, int relu)
{
    const int BM = 128, BN = 128, BK = 8;
    __shared__ float As[BK][BM];
    __shared__ float Bs[BK][BN];

    int z = blockIdx.z;
    B += (size_t)z * strideB;
    C += (size_t)z * strideC;

    int brow = blockIdx.y * BM;
    int bcol = blockIdx.x * BN;
    int tid = threadIdx.x;
    int tx = tid & 15, ty = tid >> 4;

    int arow = tid >> 1;            // 0..127
    int akk  = (tid & 1) << 2;      // 0 or 4
    int brr  = tid >> 5;            // 0..7
    int bcc  = (tid & 31) << 2;     // 0..124

    float acc[8][8];
#pragma unroll
    for (int i = 0; i < 8; i++)
#pragma unroll
        for (int j = 0; j < 8; j++) acc[i][j] = 0.f;

    for (int k0 = 0; k0 < K; k0 += BK) {
        float4 av = make_float4(0.f, 0.f, 0.f, 0.f);
        int gr = brow + arow;
        if (gr < M) av = *(const float4*)(A + (size_t)gr * K + (k0 + akk));
        As[akk + 0][arow] = av.x;
        As[akk + 1][arow] = av.y;
        As[akk + 2][arow] = av.z;
        As[akk + 3][arow] = av.w;

        float4 bv = *(const float4*)(B + (size_t)(k0 + brr) * Nc + (bcol + bcc));
        *(float4*)(&Bs[brr][bcc]) = bv;
        __syncthreads();

#pragma unroll
        for (int k = 0; k < BK; k++) {
            float ra[8], rb[8];
#pragma unroll
            for (int i = 0; i < 8; i++) ra[i] = As[k][ty * 8 + i];
#pragma unroll
            for (int j = 0; j < 8; j++) rb[j] = Bs[k][tx * 8 + j];
#pragma unroll
            for (int i = 0; i < 8; i++)
#pragma unroll
                for (int j = 0; j < 8; j++)
                    acc[i][j] = fmaf(ra[i], rb[j], acc[i][j]);
        }
        __syncthreads();
    }

#pragma unroll
    for (int i = 0; i < 8; i++) {
        int row = brow + ty * 8 + i;
        if (row >= M) continue;
#pragma unroll
        for (int j = 0; j < 8; j++) {
            int col = bcol + tx * 8 + j;
            float v = acc[i][j];
            if (bias) v += bias[col];
            if (relu) v = fmaxf(v, 0.f);
            C[(size_t)row * Nc + col] = v;
        }
    }
}

// ---------------- per-destination aggregation (CSR, no atomics) + relu ----------------
// hn already holds h @ W_loop + b. Adds sum of T[rel,src] over in-edges, applies relu.
__global__ void k_aggregate(float* __restrict__ hn, int dout) {
    int n = blockIdx.x;
    int c = threadIdx.x;
    int beg = g_rowptr[n], end = g_rowptr[n + 1];
    size_t off = (size_t)n * dout + c;
    float acc = hn[off];
    for (int e = beg; e < end; e++) {
        int s = g_esrc[e];
        int r = g_erel[e];
        acc += g_T[((size_t)r * NN + s) * dout + c];
    }
    hn[off] = fmaxf(acc, 0.f);
}

// ---------------- graph mean pooling ----------------
__global__ void k_pool(const int* __restrict__ gid, const float* __restrict__ h) {
    int n = blockIdx.x;
    int c = threadIdx.x;  // 128
    int g = gid[n];
    atomicAdd(&g_pool[g * 128 + c], h[(size_t)n * 128 + c]);
    if (c == 0) atomicAdd(&g_cnt[g], 1.0f);
}

__global__ void k_hg() {
    int g = blockIdx.x, c = threadIdx.x;
    g_hgA[g * 128 + c] = g_pool[g * 128 + c] / fmaxf(g_cnt[g], 1.0f);
}

// ---------------- classifier + softmax ----------------
__global__ void k_classifier(const float* __restrict__ hg, const float* __restrict__ Wc,
                             const float* __restrict__ bc, float* __restrict__ out) {
    int g = threadIdx.x;  // one thread per graph, 128 threads
    float logit[8];
#pragma unroll
    for (int c = 0; c < 8; c++) logit[c] = bc[c];
    const float* hr = hg + g * 128;
    for (int k = 0; k < 128; k++) {
        float hv = hr[k];
#pragma unroll
        for (int c = 0; c < 8; c++) logit[c] += hv * Wc[k * 8 + c];
    }
    float mx = logit[0];
#pragma unroll
    for (int c = 1; c < 8; c++) mx = fmaxf(mx, logit[c]);
    float s = 0.f;
#pragma unroll
    for (int c = 0; c < 8; c++) { logit[c] = expf(logit[c] - mx); s += logit[c]; }
    float inv = 1.f / s;
#pragma unroll
    for (int c = 0; c < 8; c++) out[g * 8 + c] = logit[c] * inv;
}

// ---------------- launch ----------------
extern "C" void kernel_launch(void* const* d_in, const int* in_sizes, int n_in,
                              void* d_out, int out_size) {
    const float* h  = (const float*)d_in[0];
    const int* src  = (const int*)d_in[1];
    const int* dst  = (const int*)d_in[2];
    const int* rel  = (const int*)d_in[3];
    const int* gid  = (const int*)d_in[4];
    const float* Wr[3] = {(const float*)d_in[5],  (const float*)d_in[8],  (const float*)d_in[11]};
    const float* Wl[3] = {(const float*)d_in[6],  (const float*)d_in[9],  (const float*)d_in[12]};
    const float* bb[3] = {(const float*)d_in[7],  (const float*)d_in[10], (const float*)d_in[13]};
    const float* Wh[3] = {(const float*)d_in[14], (const float*)d_in[16], (const float*)d_in[18]};
    const float* bh[3] = {(const float*)d_in[15], (const float*)d_in[17], (const float*)d_in[19]};
    const float* Wc = (const float*)d_in[20];
    const float* bc = (const float*)d_in[21];
    float* out = (float*)d_out;

    float *pT, *pHA, *pHB, *pHGA, *pHGB;
    cudaGetSymbolAddress((void**)&pT, g_T);
    cudaGetSymbolAddress((void**)&pHA, g_hA);
    cudaGetSymbolAddress((void**)&pHB, g_hB);
    cudaGetSymbolAddress((void**)&pHGA, g_hgA);
    cudaGetSymbolAddress((void**)&pHGB, g_hgB);

    // build dst-sorted CSR (reused by all 3 layers)
    k_init<<<(NN + 255) / 256, 256>>>();
    k_hist<<<(NE + 255) / 256, 256>>>(dst);
    k_scan<<<1, 1024>>>();
    k_scatter<<<(NE + 255) / 256, 256>>>(src, dst, rel);

    const int din[3] = {128, 128, 256};
    const int dou[3] = {128, 256, 128};
    const float* cur = h;
    float* nxt = pHA;
    for (int l = 0; l < 3; l++) {
        int K = din[l], Nc = dou[l];
        // T[r] = h @ W_rel[r]  (batched over 16 relations)
        dim3 gT(Nc / 128, (NN + 127) / 128, NR);
        k_gemm<<<gT, 256>>>(cur, Wr[l], nullptr, pT, NN, K, Nc,
                            (size_t)K * Nc, (size_t)NN * Nc, 0);
        // h_next = h @ W_loop + b
        dim3 gL(Nc / 128, (NN + 127) / 128, 1);
        k_gemm<<<gL, 256>>>(cur, Wl[l], bb[l], nxt, NN, K, Nc, 0, 0, 0);
        // h_next = relu(h_next + sum_in_edges T[rel, src])
        k_aggregate<<<NN, Nc>>>(nxt, Nc);
        cur = nxt;
        nxt = (nxt == pHA) ? pHB : pHA;
    }

    // graph mean pooling (cur == pHA, dim 128)
    k_pool<<<NN, 128>>>(gid, cur);
    k_hg<<<NG, 128>>>();

    // MLP head: 128 -> 128 -> 256 -> 128 (relu)
    const int mk[3] = {128, 128, 256}, mn[3] = {128, 256, 128};
    float* hin = pHGA;
    float* hout = pHGB;
    for (int l = 0; l < 3; l++) {
        dim3 g(mn[l] / 128, 1, 1);
        k_gemm<<<g, 256>>>(hin, Wh[l], bh[l], hout, NG, mk[l], mn[l], 0, 0, 1);
        float* t = hin; hin = hout; hout = t;
    }

    // classifier + softmax (hin holds final 128x128 features)
    k_classifier<<<1, NG>>>(hin, Wc, bc, out);
}

// round 2
// speedup vs baseline: 1.9659x; 1.9659x over previous
#include <cuda_runtime.h>
#include <cuda_bf16.h>
#include <cstdint>

#define NN 50000
#define NE 600000
#define NR 16
#define NG 128

// ---------------- scratch (static device globals; no allocation) ----------------
__device__ float g_T[(size_t)NR * NN * 256];   // per-relation transformed nodes (worst case dout=256)
__device__ float g_hA[(size_t)NN * 256];
__device__ float g_hB[(size_t)NN * 256];
__device__ int   g_deg[NN];
__device__ int   g_rowptr[NN + 1];
__device__ int   g_fill[NN];
__device__ int   g_esrc[NE];
__device__ int   g_erel[NE];
__device__ float g_pool[NG * 128];
__device__ float g_cnt[NG];
__device__ float g_hgA[NG * 256];
__device__ float g_hgB[NG * 256];

// ---------------- small utility kernels ----------------
__global__ void k_init() {
    int i = blockIdx.x * blockDim.x + threadIdx.x;
    if (i < NN) g_deg[i] = 0;
    if (i < NG * 128) g_pool[i] = 0.f;
    if (i < NG) g_cnt[i] = 0.f;
}

__global__ void k_hist(const int* __restrict__ dst) {
    int e = blockIdx.x * blockDim.x + threadIdx.x;
    if (e < NE) atomicAdd(&g_deg[dst[e]], 1);
}

__global__ void k_scan() {
    __shared__ int s[1024];
    int t = threadIdx.x;
    const int CH = (NN + 1023) / 1024;
    int beg = t * CH;
    int end = beg + CH; if (end > NN) end = NN;
    int sum = 0;
    for (int i = beg; i < end && i < NN; i++) sum += g_deg[i];
    s[t] = sum;
    __syncthreads();
    for (int off = 1; off < 1024; off <<= 1) {
        int v = (t >= off) ? s[t - off] : 0;
        __syncthreads();
        s[t] += v;
        __syncthreads();
    }
    int run = (t == 0) ? 0 : s[t - 1];
    for (int i = beg; i < end && i < NN; i++) {
        g_rowptr[i] = run;
        g_fill[i] = run;
        run += g_deg[i];
    }
    if (t == 1023) g_rowptr[NN] = run;
}

__global__ void k_scatter(const int* __restrict__ src, const int* __restrict__ dst,
                          const int* __restrict__ rel) {
    int e = blockIdx.x * blockDim.x + threadIdx.x;
    if (e < NE) {
        int p = atomicAdd(&g_fill[dst[e]], 1);
        g_esrc[p] = src[e];
        g_erel[p] = rel[e];
    }
}

// ---------------- tensor-core GEMM (bf16 3-pass split ~ fp32 accuracy) ----------------
// C[z] = A @ B[z] (+bias, optional relu). A:[M,K] f32, B:[K,Nc] f32, C:[M,Nc] f32.
// K % 32 == 0, Nc % 128 == 0. CTA tile 128x128, 8 warps (2x4), warp tile 64x32.
#define SA 40    // A smem row stride (bf16 elems), padded for LDSM bank spread
#define SB 136   // B smem row stride

__device__ __forceinline__ void ldsm_x4(uint32_t* r, uint32_t a) {
    asm volatile("ldmatrix.sync.aligned.m8n8.x4.shared.b16 {%0,%1,%2,%3}, [%4];"
                 : "=r"(r[0]), "=r"(r[1]), "=r"(r[2]), "=r"(r[3]) : "r"(a));
}
__device__ __forceinline__ void ldsm_x4_t(uint32_t* r, uint32_t a) {
    asm volatile("ldmatrix.sync.aligned.m8n8.x4.trans.shared.b16 {%0,%1,%2,%3}, [%4];"
                 : "=r"(r[0]), "=r"(r[1]), "=r"(r[2]), "=r"(r[3]) : "r"(a));
}
__device__ __forceinline__ void mma16816(float* c, const uint32_t* a, const uint32_t* b) {
    asm volatile("mma.sync.aligned.m16n8k16.row.col.f32.bf16.bf16.f32 "
                 "{%0,%1,%2,%3},{%4,%5,%6,%7},{%8,%9},{%0,%1,%2,%3};"
                 : "+f"(c[0]), "+f"(c[1]), "+f"(c[2]), "+f"(c[3])
                 : "r"(a[0]), "r"(a[1]), "r"(a[2]), "r"(a[3]), "r"(b[0]), "r"(b[1]));
}

__device__ __forceinline__ uint32_t pack2(uint16_t a, uint16_t b) {
    return (uint32_t)a | ((uint32_t)b << 16);
}

__global__ void __launch_bounds__(256, 1) k_gemm_tc(
    const float* __restrict__ A, const float* __restrict__ B,
    const float* __restrict__ bias, float* __restrict__ C,
    int M, int K, int Nc, size_t strideB, size_t strideC, int relu)
{
    __shared__ __align__(16) uint16_t sAh[128 * SA];
    __shared__ __align__(16) uint16_t sAl[128 * SA];
    __shared__ __align__(16) uint16_t sBh[32 * SB];
    __shared__ __align__(16) uint16_t sBl[32 * SB];

    int z = blockIdx.z;
    B += (size_t)z * strideB;
    C += (size_t)z * strideC;
    int brow = blockIdx.y * 128;
    int bcol = blockIdx.x * 128;
    int tid = threadIdx.x, lane = tid & 31, wid = tid >> 5;
    int wm = (wid >> 2) * 64;   // warp m offset within CTA tile
    int wn = (wid & 3) * 32;    // warp n offset

    float acc[4][4][4];
#pragma unroll
    for (int i = 0; i < 4; i++)
#pragma unroll
        for (int j = 0; j < 4; j++)
#pragma unroll
            for (int q = 0; q < 4; q++) acc[i][j][q] = 0.f;

    float4 pa[4], pb[4];

    // prefetch k-tile 0
    {
#pragma unroll
        for (int i = 0; i < 4; i++) {
            int id = tid + i * 256;
            int r = id >> 3, c = (id & 7) * 4;
            int gr = brow + r;
            pa[i] = (gr < M) ? *(const float4*)(A + (size_t)gr * K + c)
                             : make_float4(0.f, 0.f, 0.f, 0.f);
        }
#pragma unroll
        for (int i = 0; i < 4; i++) {
            int id = tid + i * 256;
            int r = id >> 5, c = (id & 31) * 4;
            pb[i] = *(const float4*)(B + (size_t)r * Nc + bcol + c);
        }
    }

    int ktiles = K / 32;
    for (int kt = 0; kt < ktiles; kt++) {
        // convert + store prefetched tile to smem (hi/lo split)
#pragma unroll
        for (int i = 0; i < 4; i++) {
            int id = tid + i * 256;
            int r = id >> 3, c = (id & 7) * 4;
            float x[4] = {pa[i].x, pa[i].y, pa[i].z, pa[i].w};
            uint16_t h[4], l[4];
#pragma unroll
            for (int q = 0; q < 4; q++) {
                __nv_bfloat16 hb = __float2bfloat16_rn(x[q]);
                float hf = __bfloat162float(hb);
                __nv_bfloat16 lb = __float2bfloat16_rn(x[q] - hf);
                h[q] = __bfloat16_as_ushort(hb);
                l[q] = __bfloat16_as_ushort(lb);
            }
            *(uint2*)&sAh[r * SA + c] = make_uint2(pack2(h[0], h[1]), pack2(h[2], h[3]));
            *(uint2*)&sAl[r * SA + c] = make_uint2(pack2(l[0], l[1]), pack2(l[2], l[3]));
        }
#pragma unroll
        for (int i = 0; i < 4; i++) {
            int id = tid + i * 256;
            int r = id >> 5, c = (id & 31) * 4;
            float x[4] = {pb[i].x, pb[i].y, pb[i].z, pb[i].w};
            uint16_t h[4], l[4];
#pragma unroll
            for (int q = 0; q < 4; q++) {
                __nv_bfloat16 hb = __float2bfloat16_rn(x[q]);
                float hf = __bfloat162float(hb);
                __nv_bfloat16 lb = __float2bfloat16_rn(x[q] - hf);
                h[q] = __bfloat16_as_ushort(hb);
                l[q] = __bfloat16_as_ushort(lb);
            }
            *(uint2*)&sBh[r * SB + c] = make_uint2(pack2(h[0], h[1]), pack2(h[2], h[3]));
            *(uint2*)&sBl[r * SB + c] = make_uint2(pack2(l[0], l[1]), pack2(l[2], l[3]));
        }
        __syncthreads();

        // prefetch next k-tile while MMAs run
        if (kt + 1 < ktiles) {
            int k0 = (kt + 1) * 32;
#pragma unroll
            for (int i = 0; i < 4; i++) {
                int id = tid + i * 256;
                int r = id >> 3, c = (id & 7) * 4;
                int gr = brow + r;
                pa[i] = (gr < M) ? *(const float4*)(A + (size_t)gr * K + k0 + c)
                                 : make_float4(0.f, 0.f, 0.f, 0.f);
            }
#pragma unroll
            for (int i = 0; i < 4; i++) {
                int id = tid + i * 256;
                int r = id >> 5, c = (id & 31) * 4;
                pb[i] = *(const float4*)(B + (size_t)(k0 + r) * Nc + bcol + c);
            }
        }

#pragma unroll
        for (int ks = 0; ks < 2; ks++) {
            int kk = ks * 16;
            uint32_t ah[4][4], al[4][4], bh[2][4], bl[2][4];
#pragma unroll
            for (int mt = 0; mt < 4; mt++) {
                int r = wm + mt * 16 + (lane & 15);
                int c = kk + 8 * (lane >> 4);
                ldsm_x4(ah[mt], (uint32_t)__cvta_generic_to_shared(&sAh[r * SA + c]));
                ldsm_x4(al[mt], (uint32_t)__cvta_generic_to_shared(&sAl[r * SA + c]));
            }
#pragma unroll
            for (int g = 0; g < 2; g++) {
                int r = kk + (lane & 7) + 8 * ((lane >> 3) & 1);
                int c = wn + g * 16 + 8 * (lane >> 4);
                ldsm_x4_t(bh[g], (uint32_t)__cvta_generic_to_shared(&sBh[r * SB + c]));
                ldsm_x4_t(bl[g], (uint32_t)__cvta_generic_to_shared(&sBl[r * SB + c]));
            }
#pragma unroll
            for (int mt = 0; mt < 4; mt++)
#pragma unroll
                for (int g = 0; g < 2; g++)
#pragma unroll
                    for (int hh = 0; hh < 2; hh++) {
                        int nt = g * 2 + hh;
                        mma16816(acc[mt][nt], ah[mt], &bh[g][hh * 2]);  // hi*hi
                        mma16816(acc[mt][nt], ah[mt], &bl[g][hh * 2]);  // hi*lo
                        mma16816(acc[mt][nt], al[mt], &bh[g][hh * 2]);  // lo*hi
                    }
        }
        __syncthreads();
    }

    // epilogue
#pragma unroll
    for (int mt = 0; mt < 4; mt++) {
        int r0 = brow + wm + mt * 16 + (lane >> 2);
        int r1 = r0 + 8;
#pragma unroll
        for (int nt = 0; nt < 4; nt++) {
            int c0 = bcol + wn + nt * 8 + 2 * (lane & 3);
            float b0 = 0.f, b1 = 0.f;
            if (bias) { b0 = bias[c0]; b1 = bias[c0 + 1]; }
            float v0 = acc[mt][nt][0] + b0, v1 = acc[mt][nt][1] + b1;
            float v2 = acc[mt][nt][2] + b0, v3 = acc[mt][nt][3] + b1;
            if (relu) {
                v0 = fmaxf(v0, 0.f); v1 = fmaxf(v1, 0.f);
                v2 = fmaxf(v2, 0.f); v3 = fmaxf(v3, 0.f);
            }
            if (r0 < M) *(float2*)(C + (size_t)r0 * Nc + c0) = make_float2(v0, v1);
            if (r1 < M) *(float2*)(C + (size_t)r1 * Nc + c0) = make_float2(v2, v3);
        }
    }
}

// ---------------- per-destination aggregation (CSR, no atomics) + relu ----------------
__global__ void k_aggregate(float* __restrict__ hn, int dout) {
    int n = blockIdx.x;
    int c = threadIdx.x;
    int beg = g_rowptr[n], end = g_rowptr[n + 1];
    size_t off = (size_t)n * dout + c;
    float acc = hn[off];
    for (int e = beg; e < end; e++) {
        int s = g_esrc[e];
        int r = g_erel[e];
        acc += g_T[((size_t)r * NN + s) * dout + c];
    }
    hn[off] = fmaxf(acc, 0.f);
}

// ---------------- graph mean pooling ----------------
__global__ void k_pool(const int* __restrict__ gid, const float* __restrict__ h) {
    int n = blockIdx.x;
    int c = threadIdx.x;
    int g = gid[n];
    atomicAdd(&g_pool[g * 128 + c], h[(size_t)n * 128 + c]);
    if (c == 0) atomicAdd(&g_cnt[g], 1.0f);
}

__global__ void k_hg() {
    int g = blockIdx.x, c = threadIdx.x;
    g_hgA[g * 128 + c] = g_pool[g * 128 + c] / fmaxf(g_cnt[g], 1.0f);
}

// ---------------- classifier + softmax ----------------
__global__ void k_classifier(const float* __restrict__ hg, const float* __restrict__ Wc,
                             const float* __restrict__ bc, float* __restrict__ out) {
    int g = threadIdx.x;
    float logit[8];
#pragma unroll
    for (int c = 0; c < 8; c++) logit[c] = bc[c];
    const float* hr = hg + g * 128;
    for (int k = 0; k < 128; k++) {
        float hv = hr[k];
#pragma unroll
        for (int c = 0; c < 8; c++) logit[c] += hv * Wc[k * 8 + c];
    }
    float mx = logit[0];
#pragma unroll
    for (int c = 1; c < 8; c++) mx = fmaxf(mx, logit[c]);
    float s = 0.f;
#pragma unroll
    for (int c = 0; c < 8; c++) { logit[c] = expf(logit[c] - mx); s += logit[c]; }
    float inv = 1.f / s;
#pragma unroll
    for (int c = 0; c < 8; c++) out[g * 8 + c] = logit[c] * inv;
}

// ---------------- launch ----------------
extern "C" void kernel_launch(void* const* d_in, const int* in_sizes, int n_in,
                              void* d_out, int out_size) {
    const float* h  = (const float*)d_in[0];
    const int* src  = (const int*)d_in[1];
    const int* dst  = (const int*)d_in[2];
    const int* rel  = (const int*)d_in[3];
    const int* gid  = (const int*)d_in[4];
    const float* Wr[3] = {(const float*)d_in[5],  (const float*)d_in[8],  (const float*)d_in[11]};
    const float* Wl[3] = {(const float*)d_in[6],  (const float*)d_in[9],  (const float*)d_in[12]};
    const float* bb[3] = {(const float*)d_in[7],  (const float*)d_in[10], (const float*)d_in[13]};
    const float* Wh[3] = {(const float*)d_in[14], (const float*)d_in[16], (const float*)d_in[18]};
    const float* bh[3] = {(const float*)d_in[15], (const float*)d_in[17], (const float*)d_in[19]};
    const float* Wc = (const float*)d_in[20];
    const float* bc = (const float*)d_in[21];
    float* out = (float*)d_out;

    float *pT, *pHA, *pHB, *pHGA, *pHGB;
    cudaGetSymbolAddress((void**)&pT, g_T);
    cudaGetSymbolAddress((void**)&pHA, g_hA);
    cudaGetSymbolAddress((void**)&pHB, g_hB);
    cudaGetSymbolAddress((void**)&pHGA, g_hgA);
    cudaGetSymbolAddress((void**)&pHGB, g_hgB);

    // build dst-sorted CSR (reused by all 3 layers)
    k_init<<<(NN + 255) / 256, 256>>>();
    k_hist<<<(NE + 255) / 256, 256>>>(dst);
    k_scan<<<1, 1024>>>();
    k_scatter<<<(NE + 255) / 256, 256>>>(src, dst, rel);

    const int din[3] = {128, 128, 256};
    const int dou[3] = {128, 256, 128};
    const float* cur = h;
    float* nxt = pHA;
    for (int l = 0; l < 3; l++) {
        int K = din[l], Nc = dou[l];
        // T[r] = h @ W_rel[r]  (batched over 16 relations, tensor cores)
        dim3 gT(Nc / 128, (NN + 127) / 128, NR);
        k_gemm_tc<<<gT, 256>>>(cur, Wr[l], nullptr, pT, NN, K, Nc,
                               (size_t)K * Nc, (size_t)NN * Nc, 0);
        // h_next = h @ W_loop + b
        dim3 gL(Nc / 128, (NN + 127) / 128, 1);
        k_gemm_tc<<<gL, 256>>>(cur, Wl[l], bb[l], nxt, NN, K, Nc, 0, 0, 0);
        // h_next = relu(h_next + sum_in_edges T[rel, src])
        k_aggregate<<<NN, Nc>>>(nxt, Nc);
        cur = nxt;
        nxt = (nxt == pHA) ? pHB : pHA;
    }

    // graph mean pooling
    k_pool<<<NN, 128>>>(gid, cur);
    k_hg<<<NG, 128>>>();

    // MLP head: 128 -> 128 -> 256 -> 128 (relu), tensor-core GEMMs
    const int mk[3] = {128, 128, 256}, mn[3] = {128, 256, 128};
    float* hin = pHGA;
    float* hout = pHGB;
    for (int l = 0; l < 3; l++) {
        dim3 g(mn[l] / 128, 1, 1);
        k_gemm_tc<<<g, 256>>>(hin, Wh[l], bh[l], hout, NG, mk[l], mn[l], 0, 0, 1);
        float* t = hin; hin = hout; hout = t;
    }

    // classifier + softmax
    k_classifier<<<1, NG>>>(hin, Wc, bc, out);
}

// round 3
// speedup vs baseline: 2.3088x; 1.1745x over previous
#include <cuda_runtime.h>
#include <cuda_bf16.h>
#include <cstdint>

#define NN 50000
#define NE 600000
#define NR 16
#define NG 128

// ---------------- scratch (static device globals; no allocation) ----------------
__device__ float g_T[(size_t)NR * NN * 256];   // per-relation transformed nodes
__device__ float g_hA[(size_t)NN * 256];
__device__ float g_hB[(size_t)NN * 256];
__device__ int   g_deg[NN];
__device__ int   g_rowptr[NN + 1];
__device__ int   g_fill[NN];
__device__ int   g_esrc[NE];
__device__ int   g_erel[NE];
__device__ float g_pool[NG * 128];
__device__ float g_cnt[NG];
__device__ float g_hgA[NG * 256];
__device__ float g_hgB[NG * 256];

// bf16 hi/lo split buffers (pre-converted once per layer)
__device__ uint16_t g_Ah[(size_t)NN * 256], g_Al[(size_t)NN * 256];
__device__ uint16_t g_Wrh[NR * 256 * 128], g_Wrl[NR * 256 * 128];
__device__ uint16_t g_Wlh[256 * 256], g_Wll[256 * 256];
__device__ uint16_t g_hgh[NG * 256], g_hgl[NG * 256];

// ---------------- small utility kernels ----------------
__global__ void k_init() {
    int i = blockIdx.x * blockDim.x + threadIdx.x;
    if (i < NN) g_deg[i] = 0;
    if (i < NG * 128) g_pool[i] = 0.f;
    if (i < NG) g_cnt[i] = 0.f;
}

__global__ void k_hist(const int* __restrict__ dst) {
    int e = blockIdx.x * blockDim.x + threadIdx.x;
    if (e < NE) atomicAdd(&g_deg[dst[e]], 1);
}

__global__ void k_scan() {
    __shared__ int s[1024];
    int t = threadIdx.x;
    const int CH = (NN + 1023) / 1024;
    int beg = t * CH;
    int end = beg + CH; if (end > NN) end = NN;
    int sum = 0;
    for (int i = beg; i < end && i < NN; i++) sum += g_deg[i];
    s[t] = sum;
    __syncthreads();
    for (int off = 1; off < 1024; off <<= 1) {
        int v = (t >= off) ? s[t - off] : 0;
        __syncthreads();
        s[t] += v;
        __syncthreads();
    }
    int run = (t == 0) ? 0 : s[t - 1];
    for (int i = beg; i < end && i < NN; i++) {
        g_rowptr[i] = run;
        g_fill[i] = run;
        run += g_deg[i];
    }
    if (t == 1023) g_rowptr[NN] = run;
}

__global__ void k_scatter(const int* __restrict__ src, const int* __restrict__ dst,
                          const int* __restrict__ rel) {
    int e = blockIdx.x * blockDim.x + threadIdx.x;
    if (e < NE) {
        int p = atomicAdd(&g_fill[dst[e]], 1);
        g_esrc[p] = src[e];
        g_erel[p] = rel[e];
    }
}

// ---------------- fp32 -> bf16 hi/lo split (vectorized, n % 4 == 0) ----------------
__device__ __forceinline__ uint32_t pack2(uint16_t a, uint16_t b) {
    return (uint32_t)a | ((uint32_t)b << 16);
}

__global__ void k_split(const float* __restrict__ x, uint16_t* __restrict__ hi,
                        uint16_t* __restrict__ lo, int n4) {
    int i = blockIdx.x * blockDim.x + threadIdx.x;
    if (i >= n4) return;
    float4 v = ((const float4*)x)[i];
    float f[4] = {v.x, v.y, v.z, v.w};
    uint16_t h[4], l[4];
#pragma unroll
    for (int q = 0; q < 4; q++) {
        __nv_bfloat16 hb = __float2bfloat16_rn(f[q]);
        h[q] = __bfloat16_as_ushort(hb);
        l[q] = __bfloat16_as_ushort(__float2bfloat16_rn(f[q] - __bfloat162float(hb)));
    }
    ((uint2*)hi)[i] = make_uint2(pack2(h[0], h[1]), pack2(h[2], h[3]));
    ((uint2*)lo)[i] = make_uint2(pack2(l[0], l[1]), pack2(l[2], l[3]));
}

// ---------------- tensor-core GEMM (pre-split bf16 inputs, fp32 out) ----------------
// C[z] = A @ B[z] (+bias, optional relu). K % 32 == 0, Nc % 128 == 0.
// CTA tile 128x128, 8 warps (2x4), warp tile 64x32.
#define SA 40    // A smem row stride (bf16 elems) — conflict-free LDSM phases
#define SB 136   // B smem row stride

__device__ __forceinline__ void ldsm_x4(uint32_t* r, uint32_t a) {
    asm volatile("ldmatrix.sync.aligned.m8n8.x4.shared.b16 {%0,%1,%2,%3}, [%4];"
                 : "=r"(r[0]), "=r"(r[1]), "=r"(r[2]), "=r"(r[3]) : "r"(a));
}
__device__ __forceinline__ void ldsm_x4_t(uint32_t* r, uint32_t a) {
    asm volatile("ldmatrix.sync.aligned.m8n8.x4.trans.shared.b16 {%0,%1,%2,%3}, [%4];"
                 : "=r"(r[0]), "=r"(r[1]), "=r"(r[2]), "=r"(r[3]) : "r"(a));
}
__device__ __forceinline__ void mma16816(float* c, const uint32_t* a, const uint32_t* b) {
    asm volatile("mma.sync.aligned.m16n8k16.row.col.f32.bf16.bf16.f32 "
                 "{%0,%1,%2,%3},{%4,%5,%6,%7},{%8,%9},{%0,%1,%2,%3};"
                 : "+f"(c[0]), "+f"(c[1]), "+f"(c[2]), "+f"(c[3])
                 : "r"(a[0]), "r"(a[1]), "r"(a[2]), "r"(a[3]), "r"(b[0]), "r"(b[1]));
}

__global__ void __launch_bounds__(256, 1) k_gemm_tc(
    const uint16_t* __restrict__ Ah, const uint16_t* __restrict__ Al,
    const uint16_t* __restrict__ Bh, const uint16_t* __restrict__ Bl,
    const float* __restrict__ bias, float* __restrict__ C,
    int M, int K, int Nc, size_t strideB, size_t strideC, int relu)
{
    __shared__ __align__(16) uint16_t sAh[128 * SA];
    __shared__ __align__(16) uint16_t sAl[128 * SA];
    __shared__ __align__(16) uint16_t sBh[32 * SB];
    __shared__ __align__(16) uint16_t sBl[32 * SB];

    int z = blockIdx.z;
    Bh += (size_t)z * strideB;
    Bl += (size_t)z * strideB;
    C += (size_t)z * strideC;
    int brow = blockIdx.y * 128;
    int bcol = blockIdx.x * 128;
    int tid = threadIdx.x, lane = tid & 31, wid = tid >> 5;
    int wm = (wid >> 2) * 64;
    int wn = (wid & 3) * 32;

    float acc[4][4][4];
#pragma unroll
    for (int i = 0; i < 4; i++)
#pragma unroll
        for (int j = 0; j < 4; j++)
#pragma unroll
            for (int q = 0; q < 4; q++) acc[i][j][q] = 0.f;

    // prefetch registers: A (hi,lo) 4 uint2 each; B (hi,lo) 2 uint4 each
    uint2 pah[4], pal[4];
    uint4 pbh[2], pbl[2];

    // A addressing: per-thread i in 0..3: id = tid + i*256, r=id>>3 (0..127), c=(id&7)*4
    // B addressing: per-thread i in 0..1: id = tid + i*256, r=id>>4 (0..31), c=(id&15)*8
    {
#pragma unroll
        for (int i = 0; i < 4; i++) {
            int id = tid + i * 256;
            int r = id >> 3, c = (id & 7) * 4;
            int gr = brow + r;
            if (gr < M) {
                pah[i] = *(const uint2*)(Ah + (size_t)gr * K + c);
                pal[i] = *(const uint2*)(Al + (size_t)gr * K + c);
            } else {
                pah[i] = make_uint2(0, 0);
                pal[i] = make_uint2(0, 0);
            }
        }
#pragma unroll
        for (int i = 0; i < 2; i++) {
            int id = tid + i * 256;
            int r = id >> 4, c = (id & 15) * 8;
            pbh[i] = *(const uint4*)(Bh + (size_t)r * Nc + bcol + c);
            pbl[i] = *(const uint4*)(Bl + (size_t)r * Nc + bcol + c);
        }
    }

    int ktiles = K / 32;
    for (int kt = 0; kt < ktiles; kt++) {
#pragma unroll
        for (int i = 0; i < 4; i++) {
            int id = tid + i * 256;
            int r = id >> 3, c = (id & 7) * 4;
            *(uint2*)&sAh[r * SA + c] = pah[i];
            *(uint2*)&sAl[r * SA + c] = pal[i];
        }
#pragma unroll
        for (int i = 0; i < 2; i++) {
            int id = tid + i * 256;
            int r = id >> 4, c = (id & 15) * 8;
            *(uint4*)&sBh[r * SB + c] = pbh[i];
            *(uint4*)&sBl[r * SB + c] = pbl[i];
        }
        __syncthreads();

        if (kt + 1 < ktiles) {
            int k0 = (kt + 1) * 32;
#pragma unroll
            for (int i = 0; i < 4; i++) {
                int id = tid + i * 256;
                int r = id >> 3, c = (id & 7) * 4;
                int gr = brow + r;
                if (gr < M) {
                    pah[i] = *(const uint2*)(Ah + (size_t)gr * K + k0 + c);
                    pal[i] = *(const uint2*)(Al + (size_t)gr * K + k0 + c);
                } else {
                    pah[i] = make_uint2(0, 0);
                    pal[i] = make_uint2(0, 0);
                }
            }
#pragma unroll
            for (int i = 0; i < 2; i++) {
                int id = tid + i * 256;
                int r = id >> 4, c = (id & 15) * 8;
                pbh[i] = *(const uint4*)(Bh + (size_t)(k0 + r) * Nc + bcol + c);
                pbl[i] = *(const uint4*)(Bl + (size_t)(k0 + r) * Nc + bcol + c);
            }
        }

#pragma unroll
        for (int ks = 0; ks < 2; ks++) {
            int kk = ks * 16;
            uint32_t ah[4][4], al[4][4], bh[2][4], bl[2][4];
#pragma unroll
            for (int mt = 0; mt < 4; mt++) {
                int r = wm + mt * 16 + (lane & 15);
                int c = kk + 8 * (lane >> 4);
                ldsm_x4(ah[mt], (uint32_t)__cvta_generic_to_shared(&sAh[r * SA + c]));
                ldsm_x4(al[mt], (uint32_t)__cvta_generic_to_shared(&sAl[r * SA + c]));
            }
#pragma unroll
            for (int g = 0; g < 2; g++) {
                int r = kk + (lane & 7) + 8 * ((lane >> 3) & 1);
                int c = wn + g * 16 + 8 * (lane >> 4);
                ldsm_x4_t(bh[g], (uint32_t)__cvta_generic_to_shared(&sBh[r * SB + c]));
                ldsm_x4_t(bl[g], (uint32_t)__cvta_generic_to_shared(&sBl[r * SB + c]));
            }
#pragma unroll
            for (int mt = 0; mt < 4; mt++)
#pragma unroll
                for (int g = 0; g < 2; g++)
#pragma unroll
                    for (int hh = 0; hh < 2; hh++) {
                        int nt = g * 2 + hh;
                        mma16816(acc[mt][nt], ah[mt], &bh[g][hh * 2]);  // hi*hi
                        mma16816(acc[mt][nt], ah[mt], &bl[g][hh * 2]);  // hi*lo
                        mma16816(acc[mt][nt], al[mt], &bh[g][hh * 2]);  // lo*hi
                    }
        }
        __syncthreads();
    }

    // epilogue
#pragma unroll
    for (int mt = 0; mt < 4; mt++) {
        int r0 = brow + wm + mt * 16 + (lane >> 2);
        int r1 = r0 + 8;
#pragma unroll
        for (int nt = 0; nt < 4; nt++) {
            int c0 = bcol + wn + nt * 8 + 2 * (lane & 3);
            float b0 = 0.f, b1 = 0.f;
            if (bias) { b0 = bias[c0]; b1 = bias[c0 + 1]; }
            float v0 = acc[mt][nt][0] + b0, v1 = acc[mt][nt][1] + b1;
            float v2 = acc[mt][nt][2] + b0, v3 = acc[mt][nt][3] + b1;
            if (relu) {
                v0 = fmaxf(v0, 0.f); v1 = fmaxf(v1, 0.f);
                v2 = fmaxf(v2, 0.f); v3 = fmaxf(v3, 0.f);
            }
            if (r0 < M) *(float2*)(C + (size_t)r0 * Nc + c0) = make_float2(v0, v1);
            if (r1 < M) *(float2*)(C + (size_t)r1 * Nc + c0) = make_float2(v2, v3);
        }
    }
}

// ---------------- per-destination aggregation (CSR, no atomics) + relu, float4 ----------------
__global__ void k_aggregate(float* __restrict__ hn, int dout) {
    int n = blockIdx.x;
    int c = threadIdx.x * 4;
    int beg = g_rowptr[n], end = g_rowptr[n + 1];
    size_t off = (size_t)n * dout + c;
    float4 acc = *(float4*)(hn + off);
    for (int e = beg; e < end; e++) {
        int s = g_esrc[e];
        int r = g_erel[e];
        float4 t = *(const float4*)(g_T + ((size_t)r * NN + s) * dout + c);
        acc.x += t.x; acc.y += t.y; acc.z += t.z; acc.w += t.w;
    }
    acc.x = fmaxf(acc.x, 0.f); acc.y = fmaxf(acc.y, 0.f);
    acc.z = fmaxf(acc.z, 0.f); acc.w = fmaxf(acc.w, 0.f);
    *(float4*)(hn + off) = acc;
}

// ---------------- graph mean pooling ----------------
__global__ void k_pool(const int* __restrict__ gid, const float* __restrict__ h) {
    int n = blockIdx.x;
    int c = threadIdx.x;
    int g = gid[n];
    atomicAdd(&g_pool[g * 128 + c], h[(size_t)n * 128 + c]);
    if (c == 0) atomicAdd(&g_cnt[g], 1.0f);
}

__global__ void k_hg() {
    int g = blockIdx.x, c = threadIdx.x;
    g_hgA[g * 128 + c] = g_pool[g * 128 + c] / fmaxf(g_cnt[g], 1.0f);
}

// ---------------- classifier + softmax ----------------
__global__ void k_classifier(const float* __restrict__ hg, const float* __restrict__ Wc,
                             const float* __restrict__ bc, float* __restrict__ out) {
    int g = threadIdx.x;
    float logit[8];
#pragma unroll
    for (int c = 0; c < 8; c++) logit[c] = bc[c];
    const float* hr = hg + g * 128;
    for (int k = 0; k < 128; k++) {
        float hv = hr[k];
#pragma unroll
        for (int c = 0; c < 8; c++) logit[c] += hv * Wc[k * 8 + c];
    }
    float mx = logit[0];
#pragma unroll
    for (int c = 1; c < 8; c++) mx = fmaxf(mx, logit[c]);
    float s = 0.f;
#pragma unroll
    for (int c = 0; c < 8; c++) { logit[c] = expf(logit[c] - mx); s += logit[c]; }
    float inv = 1.f / s;
#pragma unroll
    for (int c = 0; c < 8; c++) out[g * 8 + c] = logit[c] * inv;
}

// ---------------- launch ----------------
extern "C" void kernel_launch(void* const* d_in, const int* in_sizes, int n_in,
                              void* d_out, int out_size) {
    const float* h  = (const float*)d_in[0];
    const int* src  = (const int*)d_in[1];
    const int* dst  = (const int*)d_in[2];
    const int* rel  = (const int*)d_in[3];
    const int* gid  = (const int*)d_in[4];
    const float* Wr[3] = {(const float*)d_in[5],  (const float*)d_in[8],  (const float*)d_in[11]};
    const float* Wl[3] = {(const float*)d_in[6],  (const float*)d_in[9],  (const float*)d_in[12]};
    const float* bb[3] = {(const float*)d_in[7],  (const float*)d_in[10], (const float*)d_in[13]};
    const float* Wh[3] = {(const float*)d_in[14], (const float*)d_in[16], (const float*)d_in[18]};
    const float* bh[3] = {(const float*)d_in[15], (const float*)d_in[17], (const float*)d_in[19]};
    const float* Wc = (const float*)d_in[20];
    const float* bc = (const float*)d_in[21];
    float* out = (float*)d_out;

    float *pT, *pHA, *pHB, *pHGA, *pHGB;
    cudaGetSymbolAddress((void**)&pT, g_T);
    cudaGetSymbolAddress((void**)&pHA, g_hA);
    cudaGetSymbolAddress((void**)&pHB, g_hB);
    cudaGetSymbolAddress((void**)&pHGA, g_hgA);
    cudaGetSymbolAddress((void**)&pHGB, g_hgB);
    uint16_t *pAh, *pAl, *pWrh, *pWrl, *pWlh, *pWll, *pHGh, *pHGl;
    cudaGetSymbolAddress((void**)&pAh, g_Ah);
    cudaGetSymbolAddress((void**)&pAl, g_Al);
    cudaGetSymbolAddress((void**)&pWrh, g_Wrh);
    cudaGetSymbolAddress((void**)&pWrl, g_Wrl);
    cudaGetSymbolAddress((void**)&pWlh, g_Wlh);
    cudaGetSymbolAddress((void**)&pWll, g_Wll);
    cudaGetSymbolAddress((void**)&pHGh, g_hgh);
    cudaGetSymbolAddress((void**)&pHGl, g_hgl);

    // build dst-sorted CSR (reused by all 3 layers)
    k_init<<<(NN + 255) / 256, 256>>>();
    k_hist<<<(NE + 255) / 256, 256>>>(dst);
    k_scan<<<1, 1024>>>();
    k_scatter<<<(NE + 255) / 256, 256>>>(src, dst, rel);

    const int din[3] = {128, 128, 256};
    const int dou[3] = {128, 256, 128};
    const float* cur = h;
    float* nxt = pHA;
    for (int l = 0; l < 3; l++) {
        int K = din[l], Nc = dou[l];
        // pre-split inputs and weights to bf16 hi/lo
        int nA4 = NN * K / 4;
        k_split<<<(nA4 + 255) / 256, 256>>>(cur, pAh, pAl, nA4);
        int nW4 = NR * K * Nc / 4;
        k_split<<<(nW4 + 255) / 256, 256>>>(Wr[l], pWrh, pWrl, nW4);
        int nL4 = K * Nc / 4;
        k_split<<<(nL4 + 255) / 256, 256>>>(Wl[l], pWlh, pWll, nL4);

        // T[r] = h @ W_rel[r]  (batched over 16 relations)
        dim3 gT(Nc / 128, (NN + 127) / 128, NR);
        k_gemm_tc<<<gT, 256>>>(pAh, pAl, pWrh, pWrl, nullptr, pT, NN, K, Nc,
                               (size_t)K * Nc, (size_t)NN * Nc, 0);
        // h_next = h @ W_loop + b
        dim3 gL(Nc / 128, (NN + 127) / 128, 1);
        k_gemm_tc<<<gL, 256>>>(pAh, pAl, pWlh, pWll, bb[l], nxt, NN, K, Nc, 0, 0, 0);
        // h_next = relu(h_next + sum_in_edges T[rel, src])
        k_aggregate<<<NN, Nc / 4>>>(nxt, Nc);
        cur = nxt;
        nxt = (nxt == pHA) ? pHB : pHA;
    }

    // graph mean pooling
    k_pool<<<NN, 128>>>(gid, cur);
    k_hg<<<NG, 128>>>();

    // MLP head: 128 -> 128 -> 256 -> 128 (relu)
    const int mk[3] = {128, 128, 256}, mn[3] = {128, 256, 128};
    float* hin = pHGA;
    float* hout = pHGB;
    for (int l = 0; l < 3; l++) {
        int nH4 = NG * mk[l] / 4;
        k_split<<<(nH4 + 255) / 256, 256>>>(hin, pHGh, pHGl, nH4);
        int nW4 = mk[l] * mn[l] / 4;
        k_split<<<(nW4 + 255) / 256, 256>>>(Wh[l], pWlh, pWll, nW4);
        dim3 g(mn[l] / 128, 1, 1);
        k_gemm_tc<<<g, 256>>>(pHGh, pHGl, pWlh, pWll, bh[l], hout, NG, mk[l], mn[l], 0, 0, 1);
        float* t = hin; hin = hout; hout = t;
    }

    // classifier + softmax
    k_classifier<<<1, NG>>>(hin, Wc, bc, out);
}

// round 7
// speedup vs baseline: 2.9441x; 1.2752x over previous
#include <cuda_runtime.h>
#include <cuda_bf16.h>
#include <cstdint>

#define NN 50000
#define NE 600000
#define NR 16
#define NG 128

// ---------------- scratch (static device globals; no allocation) ----------------
__device__ float g_T[(size_t)NR * NN * 256];   // per-relation transformed nodes
__device__ float g_hA[(size_t)NN * 256];
__device__ float g_hB[(size_t)NN * 256];
__device__ int   g_deg[NN];
__device__ int   g_rowptr[NN + 1];
__device__ int   g_fill[NN];
__device__ int   g_epack[NE];                  // rel*NN + src, dst-sorted
__device__ float g_pool[NG * 128];
__device__ float g_cnt[NG];
__device__ float g_hgA[NG * 256];
__device__ float g_hgB[NG * 256];

// bf16 hi/lo split buffers (pre-converted once per layer)
__device__ uint16_t g_Ah[(size_t)NN * 256], g_Al[(size_t)NN * 256];
__device__ uint16_t g_Wrh[NR * 256 * 128], g_Wrl[NR * 256 * 128];
__device__ uint16_t g_Wlh[256 * 256], g_Wll[256 * 256];
__device__ uint16_t g_hgh[NG * 256], g_hgl[NG * 256];

// ---------------- small utility kernels ----------------
__global__ void k_init() {
    int i = blockIdx.x * blockDim.x + threadIdx.x;
    if (i < NN) g_deg[i] = 0;
    if (i < NG * 128) g_pool[i] = 0.f;
    if (i < NG) g_cnt[i] = 0.f;
}

__global__ void k_hist(const int* __restrict__ dst) {
    int e = blockIdx.x * blockDim.x + threadIdx.x;
    if (e < NE) atomicAdd(&g_deg[dst[e]], 1);
}

__global__ void k_scan() {
    __shared__ int s[1024];
    int t = threadIdx.x;
    const int CH = (NN + 1023) / 1024;
    int beg = t * CH;
    int end = beg + CH; if (end > NN) end = NN;
    int sum = 0;
    for (int i = beg; i < end && i < NN; i++) sum += g_deg[i];
    s[t] = sum;
    __syncthreads();
    for (int off = 1; off < 1024; off <<= 1) {
        int v = (t >= off) ? s[t - off] : 0;
        __syncthreads();
        s[t] += v;
        __syncthreads();
    }
    int run = (t == 0) ? 0 : s[t - 1];
    for (int i = beg; i < end && i < NN; i++) {
        g_rowptr[i] = run;
        g_fill[i] = run;
        run += g_deg[i];
    }
    if (t == 1023) g_rowptr[NN] = run;
}

__global__ void k_scatter(const int* __restrict__ src, const int* __restrict__ dst,
                          const int* __restrict__ rel) {
    int e = blockIdx.x * blockDim.x + threadIdx.x;
    if (e < NE) {
        int p = atomicAdd(&g_fill[dst[e]], 1);
        g_epack[p] = rel[e] * NN + src[e];
    }
}

// ---------------- fp32 -> bf16 hi/lo split (vectorized, n % 4 == 0) ----------------
__device__ __forceinline__ uint32_t pack2(uint16_t a, uint16_t b) {
    return (uint32_t)a | ((uint32_t)b << 16);
}

__global__ void k_split(const float* __restrict__ x, uint16_t* __restrict__ hi,
                        uint16_t* __restrict__ lo, int n4) {
    int i = blockIdx.x * blockDim.x + threadIdx.x;
    if (i >= n4) return;
    float4 v = ((const float4*)x)[i];
    float f[4] = {v.x, v.y, v.z, v.w};
    uint16_t h[4], l[4];
#pragma unroll
    for (int q = 0; q < 4; q++) {
        __nv_bfloat16 hb = __float2bfloat16_rn(f[q]);
        h[q] = __bfloat16_as_ushort(hb);
        l[q] = __bfloat16_as_ushort(__float2bfloat16_rn(f[q] - __bfloat162float(hb)));
    }
    ((uint2*)hi)[i] = make_uint2(pack2(h[0], h[1]), pack2(h[2], h[3]));
    ((uint2*)lo)[i] = make_uint2(pack2(l[0], l[1]), pack2(l[2], l[3]));
}

// ---------------- tensor-core GEMM, cp.async 3-stage pipeline, dynamic smem ----------------
// C[z] = A @ B[z] (+bias, optional relu). K % 32 == 0, Nc % 128 == 0.
// CTA tile 128x128x32, 8 warps (2x4), warp tile 64x32. bf16 3-pass split accum.
#define SA 40    // A smem row stride (bf16 elems)
#define SB 136   // B smem row stride

// per-stage layout (uint16 units)
#define AH_SZ (128 * SA)            // 5120
#define BH_SZ (32 * SB)             // 4352
#define STAGE_U16 (2 * AH_SZ + 2 * BH_SZ)   // 18944
#define OFF_AH 0
#define OFF_AL AH_SZ
#define OFF_BH (2 * AH_SZ)
#define OFF_BL (2 * AH_SZ + BH_SZ)
#define GEMM_SMEM_BYTES (3 * STAGE_U16 * 2) // 113664

__device__ __forceinline__ void ldsm_x4(uint32_t* r, uint32_t a) {
    asm volatile("ldmatrix.sync.aligned.m8n8.x4.shared.b16 {%0,%1,%2,%3}, [%4];"
                 : "=r"(r[0]), "=r"(r[1]), "=r"(r[2]), "=r"(r[3]) : "r"(a));
}
__device__ __forceinline__ void ldsm_x4_t(uint32_t* r, uint32_t a) {
    asm volatile("ldmatrix.sync.aligned.m8n8.x4.trans.shared.b16 {%0,%1,%2,%3}, [%4];"
                 : "=r"(r[0]), "=r"(r[1]), "=r"(r[2]), "=r"(r[3]) : "r"(a));
}
__device__ __forceinline__ void mma16816(float* c, const uint32_t* a, const uint32_t* b) {
    asm volatile("mma.sync.aligned.m16n8k16.row.col.f32.bf16.bf16.f32 "
                 "{%0,%1,%2,%3},{%4,%5,%6,%7},{%8,%9},{%0,%1,%2,%3};"
                 : "+f"(c[0]), "+f"(c[1]), "+f"(c[2]), "+f"(c[3])
                 : "r"(a[0]), "r"(a[1]), "r"(a[2]), "r"(a[3]), "r"(b[0]), "r"(b[1]));
}
__device__ __forceinline__ void cpa16(uint32_t d, const void* s, int sz) {
    asm volatile("cp.async.cg.shared.global [%0], [%1], 16, %2;"
                 :: "r"(d), "l"(s), "r"(sz));
}
__device__ __forceinline__ void cpa_commit() {
    asm volatile("cp.async.commit_group;");
}

__global__ void __launch_bounds__(256) k_gemm_tc(
    const uint16_t* __restrict__ Ah, const uint16_t* __restrict__ Al,
    const uint16_t* __restrict__ Bh, const uint16_t* __restrict__ Bl,
    const float* __restrict__ bias, float* __restrict__ C,
    int M, int K, int Nc, size_t strideB, size_t strideC, int relu)
{
    extern __shared__ __align__(16) uint16_t smem[];

    int z = blockIdx.z;
    Bh += (size_t)z * strideB;
    Bl += (size_t)z * strideB;
    C += (size_t)z * strideC;
    int brow = blockIdx.y * 128;
    int bcol = blockIdx.x * 128;
    int tid = threadIdx.x, lane = tid & 31, wid = tid >> 5;
    int wm = (wid >> 2) * 64;
    int wn = (wid & 3) * 32;

    // per-thread load coordinates
    // A: 2 chunks: id = tid + i*256; r = id>>2 (0..127), c = (id&3)*8 (0,8,16,24)
    // B: 2 chunks: id = tid + i*256; r = id>>4 (0..31),  c = (id&15)*8 (0..120)
    int ar[2], ac[2], br_[2], bc_[2];
#pragma unroll
    for (int i = 0; i < 2; i++) {
        int id = tid + i * 256;
        ar[i] = id >> 2; ac[i] = (id & 3) * 8;
        br_[i] = id >> 4; bc_[i] = (id & 15) * 8;
    }

    float acc[4][4][4];
#pragma unroll
    for (int i = 0; i < 4; i++)
#pragma unroll
        for (int j = 0; j < 4; j++)
#pragma unroll
            for (int q = 0; q < 4; q++) acc[i][j][q] = 0.f;

    int ktiles = K / 32;

    auto issue_tile = [&](int kt, int buf) {
        uint16_t* stg = smem + buf * STAGE_U16;
        int k0 = kt * 32;
#pragma unroll
        for (int i = 0; i < 2; i++) {
            int gr = brow + ar[i];
            int sz = (gr < M) ? 16 : 0;
            int grc = (gr < M) ? gr : (M - 1);
            size_t goff = (size_t)grc * K + k0 + ac[i];
            uint32_t soff = ar[i] * SA + ac[i];
            cpa16((uint32_t)__cvta_generic_to_shared(stg + OFF_AH + soff), Ah + goff, sz);
            cpa16((uint32_t)__cvta_generic_to_shared(stg + OFF_AL + soff), Al + goff, sz);
        }
#pragma unroll
        for (int i = 0; i < 2; i++) {
            size_t goff = (size_t)(k0 + br_[i]) * Nc + bcol + bc_[i];
            uint32_t soff = br_[i] * SB + bc_[i];
            cpa16((uint32_t)__cvta_generic_to_shared(stg + OFF_BH + soff), Bh + goff, 16);
            cpa16((uint32_t)__cvta_generic_to_shared(stg + OFF_BL + soff), Bl + goff, 16);
        }
        cpa_commit();
    };

    // prologue: two tiles in flight
    issue_tile(0, 0);
    if (ktiles > 1) issue_tile(1, 1);

    for (int kt = 0; kt < ktiles; kt++) {
        if (kt + 1 < ktiles) {
            asm volatile("cp.async.wait_group 1;");
        } else {
            asm volatile("cp.async.wait_group 0;");
        }
        __syncthreads();

        // issue tile kt+2 into buffer last read at iteration kt-1 (safe post-barrier)
        if (kt + 2 < ktiles) issue_tile(kt + 2, (kt + 2) % 3);

        const uint16_t* stg = smem + (kt % 3) * STAGE_U16;
        const uint16_t* bAh = stg + OFF_AH;
        const uint16_t* bAl = stg + OFF_AL;
        const uint16_t* bBh = stg + OFF_BH;
        const uint16_t* bBl = stg + OFF_BL;

#pragma unroll
        for (int ks = 0; ks < 2; ks++) {
            int kk = ks * 16;
            uint32_t ah[4][4], al[4][4], bh[2][4], bl[2][4];
#pragma unroll
            for (int mt = 0; mt < 4; mt++) {
                int r = wm + mt * 16 + (lane & 15);
                int c = kk + 8 * (lane >> 4);
                ldsm_x4(ah[mt], (uint32_t)__cvta_generic_to_shared(&bAh[r * SA + c]));
                ldsm_x4(al[mt], (uint32_t)__cvta_generic_to_shared(&bAl[r * SA + c]));
            }
#pragma unroll
            for (int g = 0; g < 2; g++) {
                int r = kk + (lane & 7) + 8 * ((lane >> 3) & 1);
                int c = wn + g * 16 + 8 * (lane >> 4);
                ldsm_x4_t(bh[g], (uint32_t)__cvta_generic_to_shared(&bBh[r * SB + c]));
                ldsm_x4_t(bl[g], (uint32_t)__cvta_generic_to_shared(&bBl[r * SB + c]));
            }
#pragma unroll
            for (int mt = 0; mt < 4; mt++)
#pragma unroll
                for (int g = 0; g < 2; g++)
#pragma unroll
                    for (int hh = 0; hh < 2; hh++) {
                        int nt = g * 2 + hh;
                        mma16816(acc[mt][nt], ah[mt], &bh[g][hh * 2]);  // hi*hi
                        mma16816(acc[mt][nt], ah[mt], &bl[g][hh * 2]);  // hi*lo
                        mma16816(acc[mt][nt], al[mt], &bh[g][hh * 2]);  // lo*hi
                    }
        }
    }

    // epilogue
#pragma unroll
    for (int mt = 0; mt < 4; mt++) {
        int r0 = brow + wm + mt * 16 + (lane >> 2);
        int r1 = r0 + 8;
#pragma unroll
        for (int nt = 0; nt < 4; nt++) {
            int c0 = bcol + wn + nt * 8 + 2 * (lane & 3);
            float b0 = 0.f, b1 = 0.f;
            if (bias) { b0 = bias[c0]; b1 = bias[c0 + 1]; }
            float v0 = acc[mt][nt][0] + b0, v1 = acc[mt][nt][1] + b1;
            float v2 = acc[mt][nt][2] + b0, v3 = acc[mt][nt][3] + b1;
            if (relu) {
                v0 = fmaxf(v0, 0.f); v1 = fmaxf(v1, 0.f);
                v2 = fmaxf(v2, 0.f); v3 = fmaxf(v3, 0.f);
            }
            if (r0 < M) *(float2*)(C + (size_t)r0 * Nc + c0) = make_float2(v0, v1);
            if (r1 < M) *(float2*)(C + (size_t)r1 * Nc + c0) = make_float2(v2, v3);
        }
    }
}

// ---------------- per-destination aggregation (CSR, no atomics) + relu ----------------
// 256-thread blocks; DOUT/4 lanes per node (warp-aligned), NPB nodes per block.
template <int DOUT>
__global__ void __launch_bounds__(256) k_aggregate(float* __restrict__ hn) {
    constexpr int LANES = DOUT / 4;       // 32 or 64
    constexpr int NPB = 256 / LANES;      // 8 or 4
    int n = blockIdx.x * NPB + threadIdx.x / LANES;
    if (n >= NN) return;
    int c = (threadIdx.x % LANES) * 4;
    int beg = g_rowptr[n], end = g_rowptr[n + 1];
    size_t off = (size_t)n * DOUT + c;
    float4 acc = *(float4*)(hn + off);
    const float* Tb = g_T + c;
#pragma unroll 4
    for (int e = beg; e < end; e++) {
        int p = g_epack[e];  // rel*NN + src
        float4 t = *(const float4*)(Tb + (size_t)p * DOUT);
        acc.x += t.x; acc.y += t.y; acc.z += t.z; acc.w += t.w;
    }
    acc.x = fmaxf(acc.x, 0.f); acc.y = fmaxf(acc.y, 0.f);
    acc.z = fmaxf(acc.z, 0.f); acc.w = fmaxf(acc.w, 0.f);
    *(float4*)(hn + off) = acc;
}

// ---------------- graph mean pooling ----------------
__global__ void k_pool(const int* __restrict__ gid, const float* __restrict__ h) {
    int n = blockIdx.x;
    int c = threadIdx.x;
    int g = gid[n];
    atomicAdd(&g_pool[g * 128 + c], h[(size_t)n * 128 + c]);
    if (c == 0) atomicAdd(&g_cnt[g], 1.0f);
}

__global__ void k_hg() {
    int g = blockIdx.x, c = threadIdx.x;
    g_hgA[g * 128 + c] = g_pool[g * 128 + c] / fmaxf(g_cnt[g], 1.0f);
}

// ---------------- classifier + softmax ----------------
__global__ void k_classifier(const float* __restrict__ hg, const float* __restrict__ Wc,
                             const float* __restrict__ bc, float* __restrict__ out) {
    int g = threadIdx.x;
    float logit[8];
#pragma unroll
    for (int c = 0; c < 8; c++) logit[c] = bc[c];
    const float* hr = hg + g * 128;
    for (int k = 0; k < 128; k++) {
        float hv = hr[k];
#pragma unroll
        for (int c = 0; c < 8; c++) logit[c] += hv * Wc[k * 8 + c];
    }
    float mx = logit[0];
#pragma unroll
    for (int c = 1; c < 8; c++) mx = fmaxf(mx, logit[c]);
    float s = 0.f;
#pragma unroll
    for (int c = 0; c < 8; c++) { logit[c] = expf(logit[c] - mx); s += logit[c]; }
    float inv = 1.f / s;
#pragma unroll
    for (int c = 0; c < 8; c++) out[g * 8 + c] = logit[c] * inv;
}

// ---------------- launch ----------------
extern "C" void kernel_launch(void* const* d_in, const int* in_sizes, int n_in,
                              void* d_out, int out_size) {
    const float* h  = (const float*)d_in[0];
    const int* src  = (const int*)d_in[1];
    const int* dst  = (const int*)d_in[2];
    const int* rel  = (const int*)d_in[3];
    const int* gid  = (const int*)d_in[4];
    const float* Wr[3] = {(const float*)d_in[5],  (const float*)d_in[8],  (const float*)d_in[11]};
    const float* Wl[3] = {(const float*)d_in[6],  (const float*)d_in[9],  (const float*)d_in[12]};
    const float* bb[3] = {(const float*)d_in[7],  (const float*)d_in[10], (const float*)d_in[13]};
    const float* Wh[3] = {(const float*)d_in[14], (const float*)d_in[16], (const float*)d_in[18]};
    const float* bh[3] = {(const float*)d_in[15], (const float*)d_in[17], (const float*)d_in[19]};
    const float* Wc = (const float*)d_in[20];
    const float* bc = (const float*)d_in[21];
    float* out = (float*)d_out;

    float *pT, *pHA, *pHB, *pHGA, *pHGB;
    cudaGetSymbolAddress((void**)&pT, g_T);
    cudaGetSymbolAddress((void**)&pHA, g_hA);
    cudaGetSymbolAddress((void**)&pHB, g_hB);
    cudaGetSymbolAddress((void**)&pHGA, g_hgA);
    cudaGetSymbolAddress((void**)&pHGB, g_hgB);
    uint16_t *pAh, *pAl, *pWrh, *pWrl, *pWlh, *pWll, *pHGh, *pHGl;
    cudaGetSymbolAddress((void**)&pAh, g_Ah);
    cudaGetSymbolAddress((void**)&pAl, g_Al);
    cudaGetSymbolAddress((void**)&pWrh, g_Wrh);
    cudaGetSymbolAddress((void**)&pWrl, g_Wrl);
    cudaGetSymbolAddress((void**)&pWlh, g_Wlh);
    cudaGetSymbolAddress((void**)&pWll, g_Wll);
    cudaGetSymbolAddress((void**)&pHGh, g_hgh);
    cudaGetSymbolAddress((void**)&pHGl, g_hgl);

    // opt-in to >48KB dynamic smem (immediate attribute set; not a stream op)
    static int smem_set = 0;
    if (!smem_set) {
        cudaFuncSetAttribute(k_gemm_tc, cudaFuncAttributeMaxDynamicSharedMemorySize,
                             GEMM_SMEM_BYTES);
        smem_set = 1;
    }

    const int din[3] = {128, 128, 256};
    const int dou[3] = {128, 256, 128};

    // layer-1 splits + T-GEMM first (puts the hot GEMM where ncu samples)
    {
        int nA4 = NN * 128 / 4;
        k_split<<<(nA4 + 255) / 256, 256>>>(h, pAh, pAl, nA4);
        int nW4 = NR * 128 * 128 / 4;
        k_split<<<(nW4 + 255) / 256, 256>>>(Wr[0], pWrh, pWrl, nW4);
        int nL4 = 128 * 128 / 4;
        k_split<<<(nL4 + 255) / 256, 256>>>(Wl[0], pWlh, pWll, nL4);
        dim3 gT(1, (NN + 127) / 128, NR);
        k_gemm_tc<<<gT, 256, GEMM_SMEM_BYTES>>>(pAh, pAl, pWrh, pWrl, nullptr, pT,
                                                NN, 128, 128,
                                                (size_t)128 * 128, (size_t)NN * 128, 0);
        dim3 gL(1, (NN + 127) / 128, 1);
        k_gemm_tc<<<gL, 256, GEMM_SMEM_BYTES>>>(pAh, pAl, pWlh, pWll, bb[0], pHA,
                                                NN, 128, 128, 0, 0, 0);
    }

    // CSR build (needed before first aggregate)
    k_init<<<(NN + 255) / 256, 256>>>();
    k_hist<<<(NE + 255) / 256, 256>>>(dst);
    k_scan<<<1, 1024>>>();
    k_scatter<<<(NE + 255) / 256, 256>>>(src, dst, rel);

    k_aggregate<128><<<(NN + 7) / 8, 256>>>(pHA);

    const float* cur = pHA;
    float* nxt = pHB;
    for (int l = 1; l < 3; l++) {
        int K = din[l], Nc = dou[l];
        int nA4 = NN * K / 4;
        k_split<<<(nA4 + 255) / 256, 256>>>(cur, pAh, pAl, nA4);
        int nW4 = NR * K * Nc / 4;
        k_split<<<(nW4 + 255) / 256, 256>>>(Wr[l], pWrh, pWrl, nW4);
        int nL4 = K * Nc / 4;
        k_split<<<(nL4 + 255) / 256, 256>>>(Wl[l], pWlh, pWll, nL4);

        dim3 gT(Nc / 128, (NN + 127) / 128, NR);
        k_gemm_tc<<<gT, 256, GEMM_SMEM_BYTES>>>(pAh, pAl, pWrh, pWrl, nullptr, pT,
                                                NN, K, Nc,
                                                (size_t)K * Nc, (size_t)NN * Nc, 0);
        dim3 gL(Nc / 128, (NN + 127) / 128, 1);
        k_gemm_tc<<<gL, 256, GEMM_SMEM_BYTES>>>(pAh, pAl, pWlh, pWll, bb[l], nxt,
                                                NN, K, Nc, 0, 0, 0);
        if (Nc == 256) k_aggregate<256><<<(NN + 3) / 4, 256>>>(nxt);
        else           k_aggregate<128><<<(NN + 7) / 8, 256>>>(nxt);
        const float* t = cur; cur = nxt; nxt = (float*)t;
        if (l == 1) nxt = (cur == pHA) ? pHB : pHA;
    }

    // graph mean pooling
    k_pool<<<NN, 128>>>(gid, cur);
    k_hg<<<NG, 128>>>();

    // MLP head: 128 -> 128 -> 256 -> 128 (relu)
    const int mk[3] = {128, 128, 256}, mn[3] = {128, 256, 128};
    float* hin = pHGA;
    float* hout = pHGB;
    for (int l = 0; l < 3; l++) {
        int nH4 = NG * mk[l] / 4;
        k_split<<<(nH4 + 255) / 256, 256>>>(hin, pHGh, pHGl, nH4);
        int nW4 = mk[l] * mn[l] / 4;
        k_split<<<(nW4 + 255) / 256, 256>>>(Wh[l], pWlh, pWll, nW4);
        dim3 g(mn[l] / 128, 1, 1);
        k_gemm_tc<<<g, 256, GEMM_SMEM_BYTES>>>(pHGh, pHGl, pWlh, pWll, bh[l], hout,
                                               NG, mk[l], mn[l], 0, 0, 1);
        float* t = hin; hin = hout; hout = t;
    }

    // classifier + softmax
    k_classifier<<<1, NG>>>(hin, Wc, bc, out);
}

// round 9
// speedup vs baseline: 4.0198x; 1.3654x over previous
#include <cuda_runtime.h>
#include <cuda_bf16.h>
#include <cstdint>

#define NN 50000
#define NE 600000
#define NR 16
#define NG 128
#define NRNN (NR * NN)          // 800000
#define NBLK ((NRNN + 1023) / 1024)  // 782

// ---------------- scratch (static device globals; no allocation) ----------------
__device__ float g_T[(size_t)NR * NN * 256];   // compact transformed rows (<=600K rows used)
__device__ float g_hA[(size_t)NN * 256];
__device__ float g_hB[(size_t)NN * 256];
__device__ int   g_deg[NN];
__device__ int   g_rowptr[NN + 1];
__device__ int   g_fill[NN];
__device__ int   g_epack[NE];                  // compact T row id per edge, dst-sorted
__device__ int   g_mark[NRNN];                 // (rel,src) occupancy
__device__ int   g_cid[NRNN + 1];              // exclusive prefix of marks (+ total)
__device__ int   g_rows[NRNN];                 // compact row -> src node id
__device__ int   g_bsum[NBLK];
__device__ float g_pool[NG * 128];
__device__ float g_cnt[NG];
__device__ float g_hgA[NG * 256];
__device__ float g_hgB[NG * 256];

// bf16 hi/lo split buffers (pre-converted once per layer)
__device__ uint16_t g_Ah[(size_t)NN * 256], g_Al[(size_t)NN * 256];
__device__ uint16_t g_Wrh[NR * 256 * 128], g_Wrl[NR * 256 * 128];
__device__ uint16_t g_Wlh[256 * 256], g_Wll[256 * 256];
__device__ uint16_t g_hgh[NG * 256], g_hgl[NG * 256];

// ---------------- init ----------------
__global__ void k_init() {
    int i = blockIdx.x * blockDim.x + threadIdx.x;
    if (i < NRNN) g_mark[i] = 0;
    if (i < NN) g_deg[i] = 0;
    if (i < NG * 128) g_pool[i] = 0.f;
    if (i < NG) g_cnt[i] = 0.f;
}

// per-edge: degree histogram + (rel,src) mark
__global__ void k_edge_prep(const int* __restrict__ src, const int* __restrict__ dst,
                            const int* __restrict__ rel) {
    int e = blockIdx.x * blockDim.x + threadIdx.x;
    if (e < NE) {
        atomicAdd(&g_deg[dst[e]], 1);
        g_mark[rel[e] * NN + src[e]] = 1;
    }
}

// ---------------- 3-kernel scan over 800K marks -> g_cid, g_rows ----------------
__global__ void k_bsum() {
    __shared__ int s[1024];
    int t = threadIdx.x;
    int i = blockIdx.x * 1024 + t;
    s[t] = (i < NRNN) ? g_mark[i] : 0;
    __syncthreads();
    for (int o = 512; o > 0; o >>= 1) {
        if (t < o) s[t] += s[t + o];
        __syncthreads();
    }
    if (t == 0) g_bsum[blockIdx.x] = s[0];
}

__global__ void k_bscan() {
    __shared__ int s[1024];
    int t = threadIdx.x;
    int v = (t < NBLK) ? g_bsum[t] : 0;
    s[t] = v;
    __syncthreads();
    for (int off = 1; off < 1024; off <<= 1) {
        int u = (t >= off) ? s[t - off] : 0;
        __syncthreads();
        s[t] += u;
        __syncthreads();
    }
    if (t < NBLK) g_bsum[t] = s[t] - v;   // exclusive
}

__global__ void k_cid() {
    __shared__ int s[1024];
    int t = threadIdx.x;
    int i = blockIdx.x * 1024 + t;
    int m = (i < NRNN) ? g_mark[i] : 0;
    s[t] = m;
    __syncthreads();
    for (int off = 1; off < 1024; off <<= 1) {
        int u = (t >= off) ? s[t - off] : 0;
        __syncthreads();
        s[t] += u;
        __syncthreads();
    }
    int excl = s[t] - m + g_bsum[blockIdx.x];
    if (i < NRNN) {
        g_cid[i] = excl;
        if (m) g_rows[excl] = i - (i / NN) * NN;   // src node id
        if (i == NRNN - 1) g_cid[NRNN] = excl + m;
    }
}

// CSR rowptr from g_deg (single-block scan over 50K)
__global__ void k_scan() {
    __shared__ int s[1024];
    int t = threadIdx.x;
    const int CH = (NN + 1023) / 1024;
    int beg = t * CH;
    int end = beg + CH; if (end > NN) end = NN;
    int sum = 0;
    for (int i = beg; i < end && i < NN; i++) sum += g_deg[i];
    s[t] = sum;
    __syncthreads();
    for (int off = 1; off < 1024; off <<= 1) {
        int v = (t >= off) ? s[t - off] : 0;
        __syncthreads();
        s[t] += v;
        __syncthreads();
    }
    int run = (t == 0) ? 0 : s[t - 1];
    for (int i = beg; i < end && i < NN; i++) {
        g_rowptr[i] = run;
        g_fill[i] = run;
        run += g_deg[i];
    }
    if (t == 1023) g_rowptr[NN] = run;
}

__global__ void k_scatter(const int* __restrict__ src, const int* __restrict__ dst,
                          const int* __restrict__ rel) {
    int e = blockIdx.x * blockDim.x + threadIdx.x;
    if (e < NE) {
        int p = atomicAdd(&g_fill[dst[e]], 1);
        g_epack[p] = g_cid[rel[e] * NN + src[e]];   // compact T row
    }
}

// ---------------- fp32 -> bf16 hi/lo split, up to 3 regions in one launch ----------------
__device__ __forceinline__ uint32_t pack2(uint16_t a, uint16_t b) {
    return (uint32_t)a | ((uint32_t)b << 16);
}

__global__ void k_split3(const float* __restrict__ x0, uint16_t* h0, uint16_t* l0, int n0,
                         const float* __restrict__ x1, uint16_t* h1, uint16_t* l1, int n1,
                         const float* __restrict__ x2, uint16_t* h2, uint16_t* l2, int n2) {
    int i = blockIdx.x * blockDim.x + threadIdx.x;
    const float* x; uint16_t* hh; uint16_t* ll; int j = i;
    if (j < n0) { x = x0; hh = h0; ll = l0; }
    else {
        j -= n0;
        if (j < n1) { x = x1; hh = h1; ll = l1; }
        else {
            j -= n1;
            if (j >= n2) return;
            x = x2; hh = h2; ll = l2;
        }
    }
    float4 v = ((const float4*)x)[j];
    float f[4] = {v.x, v.y, v.z, v.w};
    uint16_t h[4], l[4];
#pragma unroll
    for (int q = 0; q < 4; q++) {
        __nv_bfloat16 hb = __float2bfloat16_rn(f[q]);
        h[q] = __bfloat16_as_ushort(hb);
        l[q] = __bfloat16_as_ushort(__float2bfloat16_rn(f[q] - __bfloat162float(hb)));
    }
    ((uint2*)hh)[j] = make_uint2(pack2(h[0], h[1]), pack2(h[2], h[3]));
    ((uint2*)ll)[j] = make_uint2(pack2(l[0], l[1]), pack2(l[2], l[3]));
}

// ---------------- tensor-core GEMM core (cp.async 3-stage, dynamic smem) ----------------
#define SA 40
#define SB 136
#define AH_SZ (128 * SA)
#define BH_SZ (32 * SB)
#define STAGE_U16 (2 * AH_SZ + 2 * BH_SZ)
#define OFF_AH 0
#define OFF_AL AH_SZ
#define OFF_BH (2 * AH_SZ)
#define OFF_BL (2 * AH_SZ + BH_SZ)
#define GEMM_SMEM_BYTES (3 * STAGE_U16 * 2)

__device__ __forceinline__ void ldsm_x4(uint32_t* r, uint32_t a) {
    asm volatile("ldmatrix.sync.aligned.m8n8.x4.shared.b16 {%0,%1,%2,%3}, [%4];"
                 : "=r"(r[0]), "=r"(r[1]), "=r"(r[2]), "=r"(r[3]) : "r"(a));
}
__device__ __forceinline__ void ldsm_x4_t(uint32_t* r, uint32_t a) {
    asm volatile("ldmatrix.sync.aligned.m8n8.x4.trans.shared.b16 {%0,%1,%2,%3}, [%4];"
                 : "=r"(r[0]), "=r"(r[1]), "=r"(r[2]), "=r"(r[3]) : "r"(a));
}
__device__ __forceinline__ void mma16816(float* c, const uint32_t* a, const uint32_t* b) {
    asm volatile("mma.sync.aligned.m16n8k16.row.col.f32.bf16.bf16.f32 "
                 "{%0,%1,%2,%3},{%4,%5,%6,%7},{%8,%9},{%0,%1,%2,%3};"
                 : "+f"(c[0]), "+f"(c[1]), "+f"(c[2]), "+f"(c[3])
                 : "r"(a[0]), "r"(a[1]), "r"(a[2]), "r"(a[3]), "r"(b[0]), "r"(b[1]));
}
__device__ __forceinline__ void cpa16(uint32_t d, const void* s, int sz) {
    asm volatile("cp.async.cg.shared.global [%0], [%1], 16, %2;"
                 :: "r"(d), "l"(s), "r"(sz));
}
__device__ __forceinline__ void cpa_commit() {
    asm volatile("cp.async.commit_group;");
}

// shared inner machinery as a macro-free template over "indexed" flag
template <bool INDEXED>
__device__ __forceinline__ void gemm_body(
    const uint16_t* __restrict__ Ah, const uint16_t* __restrict__ Al,
    const uint16_t* __restrict__ Bh, const uint16_t* __restrict__ Bl,
    const float* __restrict__ bias, float* __restrict__ C,
    int M, int K, int Nc, int relu,
    int base, int cnt)           // for INDEXED: compact base + row count
{
    extern __shared__ __align__(16) uint16_t smem[];
    int brow = blockIdx.y * 128;
    int bcol = blockIdx.x * 128;
    int tid = threadIdx.x, lane = tid & 31, wid = tid >> 5;
    int wm = (wid >> 2) * 64;
    int wn = (wid & 3) * 32;

    int ar[2], ac[2], br_[2], bc_[2];
#pragma unroll
    for (int i = 0; i < 2; i++) {
        int id = tid + i * 256;
        ar[i] = id >> 2; ac[i] = (id & 3) * 8;
        br_[i] = id >> 4; bc_[i] = (id & 15) * 8;
    }

    // resolve A source rows once
    int asrc[2], asz[2];
#pragma unroll
    for (int i = 0; i < 2; i++) {
        int rl = brow + ar[i];
        if (INDEXED) {
            if (rl < cnt) { asrc[i] = g_rows[base + rl]; asz[i] = 16; }
            else          { asrc[i] = 0; asz[i] = 0; }
        } else {
            if (rl < M) { asrc[i] = rl; asz[i] = 16; }
            else        { asrc[i] = 0; asz[i] = 0; }
        }
    }

    float acc[4][4][4];
#pragma unroll
    for (int i = 0; i < 4; i++)
#pragma unroll
        for (int j = 0; j < 4; j++)
#pragma unroll
            for (int q = 0; q < 4; q++) acc[i][j][q] = 0.f;

    int ktiles = K / 32;

    auto issue_tile = [&](int kt, int buf) {
        uint16_t* stg = smem + buf * STAGE_U16;
        int k0 = kt * 32;
#pragma unroll
        for (int i = 0; i < 2; i++) {
            size_t goff = (size_t)asrc[i] * K + k0 + ac[i];
            uint32_t soff = ar[i] * SA + ac[i];
            cpa16((uint32_t)__cvta_generic_to_shared(stg + OFF_AH + soff), Ah + goff, asz[i]);
            cpa16((uint32_t)__cvta_generic_to_shared(stg + OFF_AL + soff), Al + goff, asz[i]);
        }
#pragma unroll
        for (int i = 0; i < 2; i++) {
            size_t goff = (size_t)(k0 + br_[i]) * Nc + bcol + bc_[i];
            uint32_t soff = br_[i] * SB + bc_[i];
            cpa16((uint32_t)__cvta_generic_to_shared(stg + OFF_BH + soff), Bh + goff, 16);
            cpa16((uint32_t)__cvta_generic_to_shared(stg + OFF_BL + soff), Bl + goff, 16);
        }
        cpa_commit();
    };

    issue_tile(0, 0);
    if (ktiles > 1) issue_tile(1, 1);

    for (int kt = 0; kt < ktiles; kt++) {
        if (kt + 1 < ktiles) {
            asm volatile("cp.async.wait_group 1;");
        } else {
            asm volatile("cp.async.wait_group 0;");
        }
        __syncthreads();
        if (kt + 2 < ktiles) issue_tile(kt + 2, (kt + 2) % 3);

        const uint16_t* stg = smem + (kt % 3) * STAGE_U16;
        const uint16_t* bAh = stg + OFF_AH;
        const uint16_t* bAl = stg + OFF_AL;
        const uint16_t* bBh = stg + OFF_BH;
        const uint16_t* bBl = stg + OFF_BL;

#pragma unroll
        for (int ks = 0; ks < 2; ks++) {
            int kk = ks * 16;
            uint32_t ah[4][4], al[4][4], bh[2][4], bl[2][4];
#pragma unroll
            for (int mt = 0; mt < 4; mt++) {
                int r = wm + mt * 16 + (lane & 15);
                int c = kk + 8 * (lane >> 4);
                ldsm_x4(ah[mt], (uint32_t)__cvta_generic_to_shared(&bAh[r * SA + c]));
                ldsm_x4(al[mt], (uint32_t)__cvta_generic_to_shared(&bAl[r * SA + c]));
            }
#pragma unroll
            for (int g = 0; g < 2; g++) {
                int r = kk + (lane & 7) + 8 * ((lane >> 3) & 1);
                int c = wn + g * 16 + 8 * (lane >> 4);
                ldsm_x4_t(bh[g], (uint32_t)__cvta_generic_to_shared(&bBh[r * SB + c]));
                ldsm_x4_t(bl[g], (uint32_t)__cvta_generic_to_shared(&bBl[r * SB + c]));
            }
#pragma unroll
            for (int mt = 0; mt < 4; mt++)
#pragma unroll
                for (int g = 0; g < 2; g++)
#pragma unroll
                    for (int hh = 0; hh < 2; hh++) {
                        int nt = g * 2 + hh;
                        mma16816(acc[mt][nt], ah[mt], &bh[g][hh * 2]);
                        mma16816(acc[mt][nt], ah[mt], &bl[g][hh * 2]);
                        mma16816(acc[mt][nt], al[mt], &bh[g][hh * 2]);
                    }
        }
    }

    // epilogue
#pragma unroll
    for (int mt = 0; mt < 4; mt++) {
        int rl0 = brow + wm + mt * 16 + (lane >> 2);
        int rl1 = rl0 + 8;
#pragma unroll
        for (int nt = 0; nt < 4; nt++) {
            int c0 = bcol + wn + nt * 8 + 2 * (lane & 3);
            float b0 = 0.f, b1 = 0.f;
            if (bias) { b0 = bias[c0]; b1 = bias[c0 + 1]; }
            float v0 = acc[mt][nt][0] + b0, v1 = acc[mt][nt][1] + b1;
            float v2 = acc[mt][nt][2] + b0, v3 = acc[mt][nt][3] + b1;
            if (relu) {
                v0 = fmaxf(v0, 0.f); v1 = fmaxf(v1, 0.f);
                v2 = fmaxf(v2, 0.f); v3 = fmaxf(v3, 0.f);
            }
            int lim = INDEXED ? cnt : M;
            int off = INDEXED ? base : 0;
            if (rl0 < lim) *(float2*)(C + (size_t)(off + rl0) * Nc + c0) = make_float2(v0, v1);
            if (rl1 < lim) *(float2*)(C + (size_t)(off + rl1) * Nc + c0) = make_float2(v2, v3);
        }
    }
}

// dense: C[z] = A @ B[z] (+bias, relu)
__global__ void __launch_bounds__(256) k_gemm_tc(
    const uint16_t* __restrict__ Ah, const uint16_t* __restrict__ Al,
    const uint16_t* __restrict__ Bh, const uint16_t* __restrict__ Bl,
    const float* __restrict__ bias, float* __restrict__ C,
    int M, int K, int Nc, size_t strideB, size_t strideC, int relu)
{
    int z = blockIdx.z;
    gemm_body<false>(Ah, Al, Bh + (size_t)z * strideB, Bl + (size_t)z * strideB,
                     bias, C + (size_t)z * strideC, M, K, Nc, relu, 0, 0);
}

// indexed: for relation z, rows g_rows[base..base+cnt), C rows compact
__global__ void __launch_bounds__(256) k_gemm_tc_idx(
    const uint16_t* __restrict__ Ah, const uint16_t* __restrict__ Al,
    const uint16_t* __restrict__ Bh, const uint16_t* __restrict__ Bl,
    float* __restrict__ C, int K, int Nc, size_t strideB)
{
    int z = blockIdx.z;
    int base = g_cid[z * NN];
    int cnt = g_cid[(z + 1) * NN] - base;
    if ((int)(blockIdx.y * 128) >= cnt) return;
    gemm_body<true>(Ah, Al, Bh + (size_t)z * strideB, Bl + (size_t)z * strideB,
                    nullptr, C, NN, K, Nc, 0, base, cnt);
}

// ---------------- per-destination aggregation (CSR, no atomics) + relu ----------------
template <int DOUT>
__global__ void __launch_bounds__(256) k_aggregate(float* __restrict__ hn) {
    constexpr int LANES = DOUT / 4;
    constexpr int NPB = 256 / LANES;
    int n = blockIdx.x * NPB + threadIdx.x / LANES;
    if (n >= NN) return;
    int c = (threadIdx.x % LANES) * 4;
    int beg = g_rowptr[n], end = g_rowptr[n + 1];
    size_t off = (size_t)n * DOUT + c;
    float4 acc = *(float4*)(hn + off);
    const float* Tb = g_T + c;
#pragma unroll 4
    for (int e = beg; e < end; e++) {
        int p = g_epack[e];
        float4 t = *(const float4*)(Tb + (size_t)p * DOUT);
        acc.x += t.x; acc.y += t.y; acc.z += t.z; acc.w += t.w;
    }
    acc.x = fmaxf(acc.x, 0.f); acc.y = fmaxf(acc.y, 0.f);
    acc.z = fmaxf(acc.z, 0.f); acc.w = fmaxf(acc.w, 0.f);
    *(float4*)(hn + off) = acc;
}

// ---------------- graph mean pooling ----------------
__global__ void k_pool(const int* __restrict__ gid, const float* __restrict__ h) {
    int n = blockIdx.x;
    int c = threadIdx.x;
    int g = gid[n];
    atomicAdd(&g_pool[g * 128 + c], h[(size_t)n * 128 + c]);
    if (c == 0) atomicAdd(&g_cnt[g], 1.0f);
}

__global__ void k_hg() {
    int g = blockIdx.x, c = threadIdx.x;
    g_hgA[g * 128 + c] = g_pool[g * 128 + c] / fmaxf(g_cnt[g], 1.0f);
}

// ---------------- classifier + softmax ----------------
__global__ void k_classifier(const float* __restrict__ hg, const float* __restrict__ Wc,
                             const float* __restrict__ bc, float* __restrict__ out) {
    int g = threadIdx.x;
    float logit[8];
#pragma unroll
    for (int c = 0; c < 8; c++) logit[c] = bc[c];
    const float* hr = hg + g * 128;
    for (int k = 0; k < 128; k++) {
        float hv = hr[k];
#pragma unroll
        for (int c = 0; c < 8; c++) logit[c] += hv * Wc[k * 8 + c];
    }
    float mx = logit[0];
#pragma unroll
    for (int c = 1; c < 8; c++) mx = fmaxf(mx, logit[c]);
    float s = 0.f;
#pragma unroll
    for (int c = 0; c < 8; c++) { logit[c] = expf(logit[c] - mx); s += logit[c]; }
    float inv = 1.f / s;
#pragma unroll
    for (int c = 0; c < 8; c++) out[g * 8 + c] = logit[c] * inv;
}

// ---------------- launch ----------------
extern "C" void kernel_launch(void* const* d_in, const int* in_sizes, int n_in,
                              void* d_out, int out_size) {
    const float* h  = (const float*)d_in[0];
    const int* src  = (const int*)d_in[1];
    const int* dst  = (const int*)d_in[2];
    const int* rel  = (const int*)d_in[3];
    const int* gid  = (const int*)d_in[4];
    const float* Wr[3] = {(const float*)d_in[5],  (const float*)d_in[8],  (const float*)d_in[11]};
    const float* Wl[3] = {(const float*)d_in[6],  (const float*)d_in[9],  (const float*)d_in[12]};
    const float* bb[3] = {(const float*)d_in[7],  (const float*)d_in[10], (const float*)d_in[13]};
    const float* Wh[3] = {(const float*)d_in[14], (const float*)d_in[16], (const float*)d_in[18]};
    const float* bh[3] = {(const float*)d_in[15], (const float*)d_in[17], (const float*)d_in[19]};
    const float* Wc = (const float*)d_in[20];
    const float* bc = (const float*)d_in[21];
    float* out = (float*)d_out;

    float *pT, *pHA, *pHB, *pHGA, *pHGB;
    cudaGetSymbolAddress((void**)&pT, g_T);
    cudaGetSymbolAddress((void**)&pHA, g_hA);
    cudaGetSymbolAddress((void**)&pHB, g_hB);
    cudaGetSymbolAddress((void**)&pHGA, g_hgA);
    cudaGetSymbolAddress((void**)&pHGB, g_hgB);
    uint16_t *pAh, *pAl, *pWrh, *pWrl, *pWlh, *pWll, *pHGh, *pHGl;
    cudaGetSymbolAddress((void**)&pAh, g_Ah);
    cudaGetSymbolAddress((void**)&pAl, g_Al);
    cudaGetSymbolAddress((void**)&pWrh, g_Wrh);
    cudaGetSymbolAddress((void**)&pWrl, g_Wrl);
    cudaGetSymbolAddress((void**)&pWlh, g_Wlh);
    cudaGetSymbolAddress((void**)&pWll, g_Wll);
    cudaGetSymbolAddress((void**)&pHGh, g_hgh);
    cudaGetSymbolAddress((void**)&pHGl, g_hgl);

    static int smem_set = 0;
    if (!smem_set) {
        cudaFuncSetAttribute(k_gemm_tc, cudaFuncAttributeMaxDynamicSharedMemorySize,
                             GEMM_SMEM_BYTES);
        cudaFuncSetAttribute(k_gemm_tc_idx, cudaFuncAttributeMaxDynamicSharedMemorySize,
                             GEMM_SMEM_BYTES);
        smem_set = 1;
    }

    const int din[3] = {128, 128, 256};
    const int dou[3] = {128, 256, 128};

    // layer-0 splits (h, Wr0, Wl0) in one launch
    {
        int n0 = NN * 128 / 4, n1 = NR * 128 * 128 / 4, n2 = 128 * 128 / 4;
        k_split3<<<(n0 + n1 + n2 + 255) / 256, 256>>>(
            h, pAh, pAl, n0, Wr[0], pWrh, pWrl, n1, Wl[0], pWlh, pWll, n2);
    }

    // compaction + CSR build
    k_init<<<(NRNN + 255) / 256, 256>>>();
    k_edge_prep<<<(NE + 255) / 256, 256>>>(src, dst, rel);
    k_bsum<<<NBLK, 1024>>>();
    k_bscan<<<1, 1024>>>();
    k_cid<<<NBLK, 1024>>>();
    k_scan<<<1, 1024>>>();
    k_scatter<<<(NE + 255) / 256, 256>>>(src, dst, rel);

    // layer 0
    {
        dim3 gT(1, (NN + 127) / 128, NR);
        k_gemm_tc_idx<<<gT, 256, GEMM_SMEM_BYTES>>>(pAh, pAl, pWrh, pWrl, pT,
                                                    128, 128, (size_t)128 * 128);
        dim3 gL(1, (NN + 127) / 128, 1);
        k_gemm_tc<<<gL, 256, GEMM_SMEM_BYTES>>>(pAh, pAl, pWlh, pWll, bb[0], pHA,
                                                NN, 128, 128, 0, 0, 0);
        k_aggregate<128><<<(NN + 7) / 8, 256>>>(pHA);
    }

    const float* cur = pHA;
    float* nxt = pHB;
    for (int l = 1; l < 3; l++) {
        int K = din[l], Nc = dou[l];
        int n0 = NN * K / 4, n1 = NR * K * Nc / 4, n2 = K * Nc / 4;
        k_split3<<<(n0 + n1 + n2 + 255) / 256, 256>>>(
            cur, pAh, pAl, n0, Wr[l], pWrh, pWrl, n1, Wl[l], pWlh, pWll, n2);

        dim3 gT(Nc / 128, (NN + 127) / 128, NR);
        k_gemm_tc_idx<<<gT, 256, GEMM_SMEM_BYTES>>>(pAh, pAl, pWrh, pWrl, pT,
                                                    K, Nc, (size_t)K * Nc);
        dim3 gL(Nc / 128, (NN + 127) / 128, 1);
        k_gemm_tc<<<gL, 256, GEMM_SMEM_BYTES>>>(pAh, pAl, pWlh, pWll, bb[l], nxt,
                                                NN, K, Nc, 0, 0, 0);
        if (Nc == 256) k_aggregate<256><<<(NN + 3) / 4, 256>>>(nxt);
        else           k_aggregate<128><<<(NN + 7) / 8, 256>>>(nxt);
        const float* t = cur; cur = nxt; nxt = (float*)t;
        if (l == 1) nxt = (cur == pHA) ? pHB : pHA;
    }

    // graph mean pooling
    k_pool<<<NN, 128>>>(gid, cur);
    k_hg<<<NG, 128>>>();

    // MLP head: 128 -> 128 -> 256 -> 128 (relu)
    const int mk[3] = {128, 128, 256}, mn[3] = {128, 256, 128};
    float* hin = pHGA;
    float* hout = pHGB;
    for (int l = 0; l < 3; l++) {
        int n0 = NG * mk[l] / 4, n1 = mk[l] * mn[l] / 4;
        k_split3<<<(n0 + n1 + 255) / 256, 256>>>(
            hin, pHGh, pHGl, n0, Wh[l], pWlh, pWll, n1, hin, pHGh, pHGl, 0);
        dim3 g(mn[l] / 128, 1, 1);
        k_gemm_tc<<<g, 256, GEMM_SMEM_BYTES>>>(pHGh, pHGl, pWlh, pWll, bh[l], hout,
                                               NG, mk[l], mn[l], 0, 0, 1);
        float* t = hin; hin = hout; hout = t;
    }

    // classifier + softmax
    k_classifier<<<1, NG>>>(hin, Wc, bc, out);
}

// round 11
// speedup vs baseline: 4.1057x; 1.0214x over previous
#include <cuda_runtime.h>
#include <cuda_bf16.h>
#include <cstdint>

#define NN 50000
#define NE 600000
#define NR 16
#define NG 128
#define NRNN (NR * NN)          // 800000
#define NBLK ((NRNN + 1023) / 1024)  // 782

// ---------------- scratch (static device globals; no allocation) ----------------
__device__ float g_T[(size_t)NR * NN * 256];   // compact transformed rows
__device__ float g_hA[(size_t)NN * 256];
__device__ float g_hB[(size_t)NN * 256];
__device__ int   g_deg[NN];
__device__ int   g_rowptr[NN + 1];
__device__ int   g_fill[NN];
__device__ int   g_epack[NE];                  // compact T row id per edge, dst-sorted
__device__ int   g_mark[NRNN];
__device__ int   g_cid[NRNN + 1];
__device__ int   g_rows[NRNN];
__device__ int   g_bsum[NBLK];
__device__ float g_pool[NG * 128];
__device__ float g_cnt[NG];
__device__ float g_hgA[NG * 256];
__device__ float g_hgB[NG * 256];

// bf16 hi/lo split buffers
__device__ uint16_t g_Ah[(size_t)NN * 256], g_Al[(size_t)NN * 256];
__device__ uint16_t g_Wrh[NR * 256 * 128], g_Wrl[NR * 256 * 128];
__device__ uint16_t g_Wlh[256 * 256], g_Wll[256 * 256];
__device__ uint16_t g_hgh[NG * 256], g_hgl[NG * 256];

// ---------------- init ----------------
__global__ void k_init() {
    int i = blockIdx.x * blockDim.x + threadIdx.x;
    if (i < NRNN) g_mark[i] = 0;
    if (i < NN) g_deg[i] = 0;
    if (i < NG * 128) g_pool[i] = 0.f;
    if (i < NG) g_cnt[i] = 0.f;
}

__global__ void k_edge_prep(const int* __restrict__ src, const int* __restrict__ dst,
                            const int* __restrict__ rel) {
    int e = blockIdx.x * blockDim.x + threadIdx.x;
    if (e < NE) {
        atomicAdd(&g_deg[dst[e]], 1);
        g_mark[rel[e] * NN + src[e]] = 1;
    }
}

// ---------------- 3-kernel scan over 800K marks -> g_cid, g_rows ----------------
__global__ void k_bsum() {
    __shared__ int s[1024];
    int t = threadIdx.x;
    int i = blockIdx.x * 1024 + t;
    s[t] = (i < NRNN) ? g_mark[i] : 0;
    __syncthreads();
    for (int o = 512; o > 0; o >>= 1) {
        if (t < o) s[t] += s[t + o];
        __syncthreads();
    }
    if (t == 0) g_bsum[blockIdx.x] = s[0];
}

__global__ void k_bscan() {
    __shared__ int s[1024];
    int t = threadIdx.x;
    int v = (t < NBLK) ? g_bsum[t] : 0;
    s[t] = v;
    __syncthreads();
    for (int off = 1; off < 1024; off <<= 1) {
        int u = (t >= off) ? s[t - off] : 0;
        __syncthreads();
        s[t] += u;
        __syncthreads();
    }
    if (t < NBLK) g_bsum[t] = s[t] - v;
}

__global__ void k_cid() {
    __shared__ int s[1024];
    int t = threadIdx.x;
    int i = blockIdx.x * 1024 + t;
    int m = (i < NRNN) ? g_mark[i] : 0;
    s[t] = m;
    __syncthreads();
    for (int off = 1; off < 1024; off <<= 1) {
        int u = (t >= off) ? s[t - off] : 0;
        __syncthreads();
        s[t] += u;
        __syncthreads();
    }
    int excl = s[t] - m + g_bsum[blockIdx.x];
    if (i < NRNN) {
        g_cid[i] = excl;
        if (m) g_rows[excl] = i - (i / NN) * NN;
        if (i == NRNN - 1) g_cid[NRNN] = excl + m;
    }
}

__global__ void k_scan() {
    __shared__ int s[1024];
    int t = threadIdx.x;
    const int CH = (NN + 1023) / 1024;
    int beg = t * CH;
    int end = beg + CH; if (end > NN) end = NN;
    int sum = 0;
    for (int i = beg; i < end && i < NN; i++) sum += g_deg[i];
    s[t] = sum;
    __syncthreads();
    for (int off = 1; off < 1024; off <<= 1) {
        int v = (t >= off) ? s[t - off] : 0;
        __syncthreads();
        s[t] += v;
        __syncthreads();
    }
    int run = (t == 0) ? 0 : s[t - 1];
    for (int i = beg; i < end && i < NN; i++) {
        g_rowptr[i] = run;
        g_fill[i] = run;
        run += g_deg[i];
    }
    if (t == 1023) g_rowptr[NN] = run;
}

__global__ void k_scatter(const int* __restrict__ src, const int* __restrict__ dst,
                          const int* __restrict__ rel) {
    int e = blockIdx.x * blockDim.x + threadIdx.x;
    if (e < NE) {
        int p = atomicAdd(&g_fill[dst[e]], 1);
        g_epack[p] = g_cid[rel[e] * NN + src[e]];
    }
}

// ---------------- fp32 -> bf16 hi/lo split, up to 3 regions ----------------
__device__ __forceinline__ uint32_t pack2(uint16_t a, uint16_t b) {
    return (uint32_t)a | ((uint32_t)b << 16);
}

__device__ __forceinline__ void split4(const float* f, uint16_t* h, uint16_t* l) {
#pragma unroll
    for (int q = 0; q < 4; q++) {
        __nv_bfloat16 hb = __float2bfloat16_rn(f[q]);
        h[q] = __bfloat16_as_ushort(hb);
        l[q] = __bfloat16_as_ushort(__float2bfloat16_rn(f[q] - __bfloat162float(hb)));
    }
}

__global__ void k_split3(const float* __restrict__ x0, uint16_t* h0, uint16_t* l0, int n0,
                         const float* __restrict__ x1, uint16_t* h1, uint16_t* l1, int n1,
                         const float* __restrict__ x2, uint16_t* h2, uint16_t* l2, int n2) {
    int i = blockIdx.x * blockDim.x + threadIdx.x;
    const float* x; uint16_t* hh; uint16_t* ll; int j = i;
    if (j < n0) { x = x0; hh = h0; ll = l0; }
    else {
        j -= n0;
        if (j < n1) { x = x1; hh = h1; ll = l1; }
        else {
            j -= n1;
            if (j >= n2) return;
            x = x2; hh = h2; ll = l2;
        }
    }
    float4 v = ((const float4*)x)[j];
    float f[4] = {v.x, v.y, v.z, v.w};
    uint16_t h[4], l[4];
    split4(f, h, l);
    ((uint2*)hh)[j] = make_uint2(pack2(h[0], h[1]), pack2(h[2], h[3]));
    ((uint2*)ll)[j] = make_uint2(pack2(l[0], l[1]), pack2(l[2], l[3]));
}

// ---------------- tensor-core GEMM core (cp.async 3-stage, dynamic smem) ----------------
#define SA 40
#define SB 136
#define AH_SZ (128 * SA)
#define BH_SZ (32 * SB)
#define STAGE_U16 (2 * AH_SZ + 2 * BH_SZ)
#define OFF_AH 0
#define OFF_AL AH_SZ
#define OFF_BH (2 * AH_SZ)
#define OFF_BL (2 * AH_SZ + BH_SZ)
#define GEMM_SMEM_BYTES (3 * STAGE_U16 * 2)

__device__ __forceinline__ void ldsm_x4(uint32_t* r, uint32_t a) {
    asm volatile("ldmatrix.sync.aligned.m8n8.x4.shared.b16 {%0,%1,%2,%3}, [%4];"
                 : "=r"(r[0]), "=r"(r[1]), "=r"(r[2]), "=r"(r[3]) : "r"(a));
}
__device__ __forceinline__ void ldsm_x4_t(uint32_t* r, uint32_t a) {
    asm volatile("ldmatrix.sync.aligned.m8n8.x4.trans.shared.b16 {%0,%1,%2,%3}, [%4];"
                 : "=r"(r[0]), "=r"(r[1]), "=r"(r[2]), "=r"(r[3]) : "r"(a));
}
__device__ __forceinline__ void mma16816(float* c, const uint32_t* a, const uint32_t* b) {
    asm volatile("mma.sync.aligned.m16n8k16.row.col.f32.bf16.bf16.f32 "
                 "{%0,%1,%2,%3},{%4,%5,%6,%7},{%8,%9},{%0,%1,%2,%3};"
                 : "+f"(c[0]), "+f"(c[1]), "+f"(c[2]), "+f"(c[3])
                 : "r"(a[0]), "r"(a[1]), "r"(a[2]), "r"(a[3]), "r"(b[0]), "r"(b[1]));
}
__device__ __forceinline__ void cpa16(uint32_t d, const void* s, int sz) {
    asm volatile("cp.async.cg.shared.global [%0], [%1], 16, %2;"
                 :: "r"(d), "l"(s), "r"(sz));
}
__device__ __forceinline__ void cpa_commit() {
    asm volatile("cp.async.commit_group;");
}

template <bool INDEXED>
__device__ __forceinline__ void gemm_body(
    const uint16_t* __restrict__ Ah, const uint16_t* __restrict__ Al,
    const uint16_t* __restrict__ Bh, const uint16_t* __restrict__ Bl,
    const float* __restrict__ bias, float* __restrict__ C,
    int M, int K, int Nc, int relu,
    int base, int cnt)
{
    extern __shared__ __align__(16) uint16_t smem[];
    int brow = blockIdx.y * 128;
    int bcol = blockIdx.x * 128;
    int tid = threadIdx.x, lane = tid & 31, wid = tid >> 5;
    int wm = (wid >> 2) * 64;
    int wn = (wid & 3) * 32;

    int ar[2], ac[2], br_[2], bc_[2];
#pragma unroll
    for (int i = 0; i < 2; i++) {
        int id = tid + i * 256;
        ar[i] = id >> 2; ac[i] = (id & 3) * 8;
        br_[i] = id >> 4; bc_[i] = (id & 15) * 8;
    }

    int asrc[2], asz[2];
#pragma unroll
    for (int i = 0; i < 2; i++) {
        int rl = brow + ar[i];
        if (INDEXED) {
            if (rl < cnt) { asrc[i] = g_rows[base + rl]; asz[i] = 16; }
            else          { asrc[i] = 0; asz[i] = 0; }
        } else {
            if (rl < M) { asrc[i] = rl; asz[i] = 16; }
            else        { asrc[i] = 0; asz[i] = 0; }
        }
    }

    float acc[4][4][4];
#pragma unroll
    for (int i = 0; i < 4; i++)
#pragma unroll
        for (int j = 0; j < 4; j++)
#pragma unroll
            for (int q = 0; q < 4; q++) acc[i][j][q] = 0.f;

    int ktiles = K / 32;

    auto issue_tile = [&](int kt, int buf) {
        uint16_t* stg = smem + buf * STAGE_U16;
        int k0 = kt * 32;
#pragma unroll
        for (int i = 0; i < 2; i++) {
            size_t goff = (size_t)asrc[i] * K + k0 + ac[i];
            uint32_t soff = ar[i] * SA + ac[i];
            cpa16((uint32_t)__cvta_generic_to_shared(stg + OFF_AH + soff), Ah + goff, asz[i]);
            cpa16((uint32_t)__cvta_generic_to_shared(stg + OFF_AL + soff), Al + goff, asz[i]);
        }
#pragma unroll
        for (int i = 0; i < 2; i++) {
            size_t goff = (size_t)(k0 + br_[i]) * Nc + bcol + bc_[i];
            uint32_t soff = br_[i] * SB + bc_[i];
            cpa16((uint32_t)__cvta_generic_to_shared(stg + OFF_BH + soff), Bh + goff, 16);
            cpa16((uint32_t)__cvta_generic_to_shared(stg + OFF_BL + soff), Bl + goff, 16);
        }
        cpa_commit();
    };

    issue_tile(0, 0);
    if (ktiles > 1) issue_tile(1, 1);

    for (int kt = 0; kt < ktiles; kt++) {
        if (kt + 1 < ktiles) {
            asm volatile("cp.async.wait_group 1;");
        } else {
            asm volatile("cp.async.wait_group 0;");
        }
        __syncthreads();
        if (kt + 2 < ktiles) issue_tile(kt + 2, (kt + 2) % 3);

        const uint16_t* stg = smem + (kt % 3) * STAGE_U16;
        const uint16_t* bAh = stg + OFF_AH;
        const uint16_t* bAl = stg + OFF_AL;
        const uint16_t* bBh = stg + OFF_BH;
        const uint16_t* bBl = stg + OFF_BL;

#pragma unroll
        for (int ks = 0; ks < 2; ks++) {
            int kk = ks * 16;
            uint32_t ah[4][4], al[4][4], bh[2][4], bl[2][4];
#pragma unroll
            for (int mt = 0; mt < 4; mt++) {
                int r = wm + mt * 16 + (lane & 15);
                int c = kk + 8 * (lane >> 4);
                ldsm_x4(ah[mt], (uint32_t)__cvta_generic_to_shared(&bAh[r * SA + c]));
                ldsm_x4(al[mt], (uint32_t)__cvta_generic_to_shared(&bAl[r * SA + c]));
            }
#pragma unroll
            for (int g = 0; g < 2; g++) {
                int r = kk + (lane & 7) + 8 * ((lane >> 3) & 1);
                int c = wn + g * 16 + 8 * (lane >> 4);
                ldsm_x4_t(bh[g], (uint32_t)__cvta_generic_to_shared(&bBh[r * SB + c]));
                ldsm_x4_t(bl[g], (uint32_t)__cvta_generic_to_shared(&bBl[r * SB + c]));
            }
            // pass-major order: 16 independent accumulators between reuses —
            // hides HMMA latency (was a 3-deep dependent chain per acc tile)
#pragma unroll
            for (int mt = 0; mt < 4; mt++)
#pragma unroll
                for (int g = 0; g < 2; g++)
#pragma unroll
                    for (int hh = 0; hh < 2; hh++)
                        mma16816(acc[mt][g * 2 + hh], ah[mt], &bh[g][hh * 2]);  // hi*hi
#pragma unroll
            for (int mt = 0; mt < 4; mt++)
#pragma unroll
                for (int g = 0; g < 2; g++)
#pragma unroll
                    for (int hh = 0; hh < 2; hh++)
                        mma16816(acc[mt][g * 2 + hh], ah[mt], &bl[g][hh * 2]);  // hi*lo
#pragma unroll
            for (int mt = 0; mt < 4; mt++)
#pragma unroll
                for (int g = 0; g < 2; g++)
#pragma unroll
                    for (int hh = 0; hh < 2; hh++)
                        mma16816(acc[mt][g * 2 + hh], al[mt], &bh[g][hh * 2]);  // lo*hi
        }
    }

    // epilogue
#pragma unroll
    for (int mt = 0; mt < 4; mt++) {
        int rl0 = brow + wm + mt * 16 + (lane >> 2);
        int rl1 = rl0 + 8;
#pragma unroll
        for (int nt = 0; nt < 4; nt++) {
            int c0 = bcol + wn + nt * 8 + 2 * (lane & 3);
            float b0 = 0.f, b1 = 0.f;
            if (bias) { b0 = bias[c0]; b1 = bias[c0 + 1]; }
            float v0 = acc[mt][nt][0] + b0, v1 = acc[mt][nt][1] + b1;
            float v2 = acc[mt][nt][2] + b0, v3 = acc[mt][nt][3] + b1;
            if (relu) {
                v0 = fmaxf(v0, 0.f); v1 = fmaxf(v1, 0.f);
                v2 = fmaxf(v2, 0.f); v3 = fmaxf(v3, 0.f);
            }
            int lim = INDEXED ? cnt : M;
            int off = INDEXED ? base : 0;
            if (rl0 < lim) *(float2*)(C + (size_t)(off + rl0) * Nc + c0) = make_float2(v0, v1);
            if (rl1 < lim) *(float2*)(C + (size_t)(off + rl1) * Nc + c0) = make_float2(v2, v3);
        }
    }
}

__global__ void __launch_bounds__(256) k_gemm_tc(
    const uint16_t* __restrict__ Ah, const uint16_t* __restrict__ Al,
    const uint16_t* __restrict__ Bh, const uint16_t* __restrict__ Bl,
    const float* __restrict__ bias, float* __restrict__ C,
    int M, int K, int Nc, size_t strideB, size_t strideC, int relu)
{
    int z = blockIdx.z;
    gemm_body<false>(Ah, Al, Bh + (size_t)z * strideB, Bl + (size_t)z * strideB,
                     bias, C + (size_t)z * strideC, M, K, Nc, relu, 0, 0);
}

__global__ void __launch_bounds__(256) k_gemm_tc_idx(
    const uint16_t* __restrict__ Ah, const uint16_t* __restrict__ Al,
    const uint16_t* __restrict__ Bh, const uint16_t* __restrict__ Bl,
    float* __restrict__ C, int K, int Nc, size_t strideB)
{
    int z = blockIdx.z;
    int base = g_cid[z * NN];
    int cnt = g_cid[(z + 1) * NN] - base;
    if ((int)(blockIdx.y * 128) >= cnt) return;
    gemm_body<true>(Ah, Al, Bh + (size_t)z * strideB, Bl + (size_t)z * strideB,
                    nullptr, C, NN, K, Nc, 0, base, cnt);
}

// ---------------- aggregation (CSR, no atomics) + relu, fused output format ----------------
// MODE 0: write fp32 to hn_out. MODE 1: write bf16 hi/lo split to oh/ol.
template <int DOUT, int MODE>
__global__ void __launch_bounds__(256) k_aggregate(const float* __restrict__ hn_in,
                                                   float* __restrict__ hn_out,
                                                   uint16_t* __restrict__ oh,
                                                   uint16_t* __restrict__ ol) {
    constexpr int LANES = DOUT / 4;
    constexpr int NPB = 256 / LANES;
    int n = blockIdx.x * NPB + threadIdx.x / LANES;
    if (n >= NN) return;
    int c = (threadIdx.x % LANES) * 4;
    int beg = g_rowptr[n], end = g_rowptr[n + 1];
    size_t off = (size_t)n * DOUT + c;
    float4 acc = __ldg((const float4*)(hn_in + off));
    const float* Tb = g_T + c;
#pragma unroll 4
    for (int e = beg; e < end; e++) {
        int p = g_epack[e];
        float4 t = __ldg((const float4*)(Tb + (size_t)p * DOUT));
        acc.x += t.x; acc.y += t.y; acc.z += t.z; acc.w += t.w;
    }
    acc.x = fmaxf(acc.x, 0.f); acc.y = fmaxf(acc.y, 0.f);
    acc.z = fmaxf(acc.z, 0.f); acc.w = fmaxf(acc.w, 0.f);
    if (MODE == 0) {
        *(float4*)(hn_out + off) = acc;
    } else {
        float f[4] = {acc.x, acc.y, acc.z, acc.w};
        uint16_t h[4], l[4];
        split4(f, h, l);
        ((uint2*)oh)[off / 4] = make_uint2(pack2(h[0], h[1]), pack2(h[2], h[3]));
        ((uint2*)ol)[off / 4] = make_uint2(pack2(l[0], l[1]), pack2(l[2], l[3]));
    }
}

// ---------------- graph mean pooling ----------------
__global__ void k_pool(const int* __restrict__ gid, const float* __restrict__ h) {
    int n = blockIdx.x;
    int c = threadIdx.x;
    int g = gid[n];
    atomicAdd(&g_pool[g * 128 + c], h[(size_t)n * 128 + c]);
    if (c == 0) atomicAdd(&g_cnt[g], 1.0f);
}

__global__ void k_hg() {
    int g = blockIdx.x, c = threadIdx.x;
    g_hgA[g * 128 + c] = g_pool[g * 128 + c] / fmaxf(g_cnt[g], 1.0f);
}

// ---------------- classifier + softmax ----------------
__global__ void k_classifier(const float* __restrict__ hg, const float* __restrict__ Wc,
                             const float* __restrict__ bc, float* __restrict__ out) {
    int g = threadIdx.x;
    float logit[8];
#pragma unroll
    for (int c = 0; c < 8; c++) logit[c] = bc[c];
    const float* hr = hg + g * 128;
    for (int k = 0; k < 128; k++) {
        float hv = hr[k];
#pragma unroll
        for (int c = 0; c < 8; c++) logit[c] += hv * Wc[k * 8 + c];
    }
    float mx = logit[0];
#pragma unroll
    for (int c = 1; c < 8; c++) mx = fmaxf(mx, logit[c]);
    float s = 0.f;
#pragma unroll
    for (int c = 0; c < 8; c++) { logit[c] = expf(logit[c] - mx); s += logit[c]; }
    float inv = 1.f / s;
#pragma unroll
    for (int c = 0; c < 8; c++) out[g * 8 + c] = logit[c] * inv;
}

// ---------------- launch ----------------
extern "C" void kernel_launch(void* const* d_in, const int* in_sizes, int n_in,
                              void* d_out, int out_size) {
    const float* h  = (const float*)d_in[0];
    const int* src  = (const int*)d_in[1];
    const int* dst  = (const int*)d_in[2];
    const int* rel  = (const int*)d_in[3];
    const int* gid  = (const int*)d_in[4];
    const float* Wr[3] = {(const float*)d_in[5],  (const float*)d_in[8],  (const float*)d_in[11]};
    const float* Wl[3] = {(const float*)d_in[6],  (const float*)d_in[9],  (const float*)d_in[12]};
    const float* bb[3] = {(const float*)d_in[7],  (const float*)d_in[10], (const float*)d_in[13]};
    const float* Wh[3] = {(const float*)d_in[14], (const float*)d_in[16], (const float*)d_in[18]};
    const float* bh[3] = {(const float*)d_in[15], (const float*)d_in[17], (const float*)d_in[19]};
    const float* Wc = (const float*)d_in[20];
    const float* bc = (const float*)d_in[21];
    float* out = (float*)d_out;

    float *pT, *pHA, *pHB, *pHGA, *pHGB;
    cudaGetSymbolAddress((void**)&pT, g_T);
    cudaGetSymbolAddress((void**)&pHA, g_hA);
    cudaGetSymbolAddress((void**)&pHB, g_hB);
    cudaGetSymbolAddress((void**)&pHGA, g_hgA);
    cudaGetSymbolAddress((void**)&pHGB, g_hgB);
    uint16_t *pAh, *pAl, *pWrh, *pWrl, *pWlh, *pWll, *pHGh, *pHGl;
    cudaGetSymbolAddress((void**)&pAh, g_Ah);
    cudaGetSymbolAddress((void**)&pAl, g_Al);
    cudaGetSymbolAddress((void**)&pWrh, g_Wrh);
    cudaGetSymbolAddress((void**)&pWrl, g_Wrl);
    cudaGetSymbolAddress((void**)&pWlh, g_Wlh);
    cudaGetSymbolAddress((void**)&pWll, g_Wll);
    cudaGetSymbolAddress((void**)&pHGh, g_hgh);
    cudaGetSymbolAddress((void**)&pHGl, g_hgl);

    static int smem_set = 0;
    if (!smem_set) {
        cudaFuncSetAttribute(k_gemm_tc, cudaFuncAttributeMaxDynamicSharedMemorySize,
                             GEMM_SMEM_BYTES);
        cudaFuncSetAttribute(k_gemm_tc_idx, cudaFuncAttributeMaxDynamicSharedMemorySize,
                             GEMM_SMEM_BYTES);
        smem_set = 1;
    }

    // 1: split h + layer-0 weights
    {
        int n0 = NN * 128 / 4, n1 = NR * 128 * 128 / 4, n2 = 128 * 128 / 4;
        k_split3<<<(n0 + n1 + n2 + 255) / 256, 256>>>(
            h, pAh, pAl, n0, Wr[0], pWrh, pWrl, n1, Wl[0], pWlh, pWll, n2);
    }
    // 2-3: init + edge prep
    k_init<<<(NRNN + 255) / 256, 256>>>();
    k_edge_prep<<<(NE + 255) / 256, 256>>>(src, dst, rel);
    // 4: dense loop GEMM layer 0 (profiled slot)
    {
        dim3 gL(1, (NN + 127) / 128, 1);
        k_gemm_tc<<<gL, 256, GEMM_SMEM_BYTES>>>(pAh, pAl, pWlh, pWll, bb[0], pHA,
                                                NN, 128, 128, 0, 0, 0);
    }
    // compaction + CSR
    k_bsum<<<NBLK, 1024>>>();
    k_bscan<<<1, 1024>>>();
    k_cid<<<NBLK, 1024>>>();
    k_scan<<<1, 1024>>>();
    k_scatter<<<(NE + 255) / 256, 256>>>(src, dst, rel);

    // layer 0: T-GEMM + aggregate (emit bf16 directly)
    {
        dim3 gT(1, (NN + 127) / 128, NR);
        k_gemm_tc_idx<<<gT, 256, GEMM_SMEM_BYTES>>>(pAh, pAl, pWrh, pWrl, pT,
                                                    128, 128, (size_t)128 * 128);
        k_aggregate<128, 1><<<(NN + 7) / 8, 256>>>(pHA, nullptr, pAh, pAl);
    }

    // layer 1: K=128 -> Nc=256
    {
        int n1 = NR * 128 * 256 / 4, n2 = 128 * 256 / 4;
        k_split3<<<(n1 + n2 + 255) / 256, 256>>>(
            Wr[1], pWrh, pWrl, n1, Wl[1], pWlh, pWll, n2, nullptr, nullptr, nullptr, 0);
        dim3 gT(2, (NN + 127) / 128, NR);
        k_gemm_tc_idx<<<gT, 256, GEMM_SMEM_BYTES>>>(pAh, pAl, pWrh, pWrl, pT,
                                                    128, 256, (size_t)128 * 256);
        dim3 gL(2, (NN + 127) / 128, 1);
        k_gemm_tc<<<gL, 256, GEMM_SMEM_BYTES>>>(pAh, pAl, pWlh, pWll, bb[1], pHA,
                                                NN, 128, 256, 0, 0, 0);
        k_aggregate<256, 1><<<(NN + 3) / 4, 256>>>(pHA, nullptr, pAh, pAl);
    }

    // layer 2: K=256 -> Nc=128 (emit fp32 for pooling)
    {
        int n1 = NR * 256 * 128 / 4, n2 = 256 * 128 / 4;
        k_split3<<<(n1 + n2 + 255) / 256, 256>>>(
            Wr[2], pWrh, pWrl, n1, Wl[2], pWlh, pWll, n2, nullptr, nullptr, nullptr, 0);
        dim3 gT(1, (NN + 127) / 128, NR);
        k_gemm_tc_idx<<<gT, 256, GEMM_SMEM_BYTES>>>(pAh, pAl, pWrh, pWrl, pT,
                                                    256, 128, (size_t)256 * 128);
        dim3 gL(1, (NN + 127) / 128, 1);
        k_gemm_tc<<<gL, 256, GEMM_SMEM_BYTES>>>(pAh, pAl, pWlh, pWll, bb[2], pHB,
                                                NN, 256, 128, 0, 0, 0);
        k_aggregate<128, 0><<<(NN + 7) / 8, 256>>>(pHB, pHB, nullptr, nullptr);
    }

    // graph mean pooling
    k_pool<<<NN, 128>>>(gid, pHB);
    k_hg<<<NG, 128>>>();

    // MLP head: 128 -> 128 -> 256 -> 128 (relu)
    const int mk[3] = {128, 128, 256}, mn[3] = {128, 256, 128};
    float* hin = pHGA;
    float* hout = pHGB;
    for (int l = 0; l < 3; l++) {
        int n0 = NG * mk[l] / 4, n1 = mk[l] * mn[l] / 4;
        k_split3<<<(n0 + n1 + 255) / 256, 256>>>(
            hin, pHGh, pHGl, n0, Wh[l], pWlh, pWll, n1, nullptr, nullptr, nullptr, 0);
        dim3 g(mn[l] / 128, 1, 1);
        k_gemm_tc<<<g, 256, GEMM_SMEM_BYTES>>>(pHGh, pHGl, pWlh, pWll, bh[l], hout,
                                               NG, mk[l], mn[l], 0, 0, 1);
        float* t = hin; hin = hout; hout = t;
    }

    // classifier + softmax
    k_classifier<<<1, NG>>>(hin, Wc, bc, out);
}

// round 13
// speedup vs baseline: 4.4894x; 1.0935x over previous
#include <cuda_runtime.h>
#include <cuda_bf16.h>
#include <cuda_fp16.h>
#include <cstdint>

#define NN 50000
#define NE 600000
#define NR 16
#define NG 128
#define NRNN (NR * NN)          // 800000
#define NBLK ((NRNN + 1023) / 1024)  // 782
#define MAXROWS 600000          // compact T rows <= NE

// ---------------- scratch (static device globals; no allocation) ----------------
__device__ __half g_T[(size_t)MAXROWS * 256];  // compact transformed rows, fp16
__device__ float g_hA[(size_t)NN * 256];
__device__ float g_hB[(size_t)NN * 256];
__device__ int   g_deg[NN];
__device__ int   g_rowptr[NN + 1];
__device__ int   g_fill[NN];
__device__ int   g_epack[NE];                  // compact T row id per edge, dst-sorted
__device__ int   g_mark[NRNN];
__device__ int   g_cid[NRNN + 1];
__device__ int   g_rows[NRNN];
__device__ int   g_bsum[NBLK];
__device__ float g_pool[NG * 128];
__device__ float g_cnt[NG];
__device__ float g_hgA[NG * 256];
__device__ float g_hgB[NG * 256];

// bf16 hi/lo split buffers
__device__ uint16_t g_Ah[(size_t)NN * 256], g_Al[(size_t)NN * 256];
__device__ uint16_t g_Wrh[NR * 256 * 128], g_Wrl[NR * 256 * 128];
__device__ uint16_t g_Wlh[256 * 256], g_Wll[256 * 256];
__device__ uint16_t g_hgh[NG * 256], g_hgl[NG * 256];

// ---------------- init ----------------
__global__ void k_init() {
    int i = blockIdx.x * blockDim.x + threadIdx.x;
    if (i < NRNN) g_mark[i] = 0;
    if (i < NN) g_deg[i] = 0;
    if (i < NG * 128) g_pool[i] = 0.f;
    if (i < NG) g_cnt[i] = 0.f;
}

__global__ void k_edge_prep(const int* __restrict__ src, const int* __restrict__ dst,
                            const int* __restrict__ rel) {
    int e = blockIdx.x * blockDim.x + threadIdx.x;
    if (e < NE) {
        atomicAdd(&g_deg[dst[e]], 1);
        g_mark[rel[e] * NN + src[e]] = 1;
    }
}

// ---------------- 3-kernel scan over 800K marks -> g_cid, g_rows ----------------
__global__ void k_bsum() {
    __shared__ int s[1024];
    int t = threadIdx.x;
    int i = blockIdx.x * 1024 + t;
    s[t] = (i < NRNN) ? g_mark[i] : 0;
    __syncthreads();
    for (int o = 512; o > 0; o >>= 1) {
        if (t < o) s[t] += s[t + o];
        __syncthreads();
    }
    if (t == 0) g_bsum[blockIdx.x] = s[0];
}

__global__ void k_bscan() {
    __shared__ int s[1024];
    int t = threadIdx.x;
    int v = (t < NBLK) ? g_bsum[t] : 0;
    s[t] = v;
    __syncthreads();
    for (int off = 1; off < 1024; off <<= 1) {
        int u = (t >= off) ? s[t - off] : 0;
        __syncthreads();
        s[t] += u;
        __syncthreads();
    }
    if (t < NBLK) g_bsum[t] = s[t] - v;
}

__global__ void k_cid() {
    __shared__ int s[1024];
    int t = threadIdx.x;
    int i = blockIdx.x * 1024 + t;
    int m = (i < NRNN) ? g_mark[i] : 0;
    s[t] = m;
    __syncthreads();
    for (int off = 1; off < 1024; off <<= 1) {
        int u = (t >= off) ? s[t - off] : 0;
        __syncthreads();
        s[t] += u;
        __syncthreads();
    }
    int excl = s[t] - m + g_bsum[blockIdx.x];
    if (i < NRNN) {
        g_cid[i] = excl;
        if (m) g_rows[excl] = i - (i / NN) * NN;
        if (i == NRNN - 1) g_cid[NRNN] = excl + m;
    }
}

__global__ void k_scan() {
    __shared__ int s[1024];
    int t = threadIdx.x;
    const int CH = (NN + 1023) / 1024;
    int beg = t * CH;
    int end = beg + CH; if (end > NN) end = NN;
    int sum = 0;
    for (int i = beg; i < end && i < NN; i++) sum += g_deg[i];
    s[t] = sum;
    __syncthreads();
    for (int off = 1; off < 1024; off <<= 1) {
        int v = (t >= off) ? s[t - off] : 0;
        __syncthreads();
        s[t] += v;
        __syncthreads();
    }
    int run = (t == 0) ? 0 : s[t - 1];
    for (int i = beg; i < end && i < NN; i++) {
        g_rowptr[i] = run;
        g_fill[i] = run;
        run += g_deg[i];
    }
    if (t == 1023) g_rowptr[NN] = run;
}

__global__ void k_scatter(const int* __restrict__ src, const int* __restrict__ dst,
                          const int* __restrict__ rel) {
    int e = blockIdx.x * blockDim.x + threadIdx.x;
    if (e < NE) {
        int p = atomicAdd(&g_fill[dst[e]], 1);
        g_epack[p] = g_cid[rel[e] * NN + src[e]];
    }
}

// ---------------- fp32 -> bf16 hi/lo split, up to 3 regions ----------------
__device__ __forceinline__ uint32_t pack2(uint16_t a, uint16_t b) {
    return (uint32_t)a | ((uint32_t)b << 16);
}

__device__ __forceinline__ void split4(const float* f, uint16_t* h, uint16_t* l) {
#pragma unroll
    for (int q = 0; q < 4; q++) {
        __nv_bfloat16 hb = __float2bfloat16_rn(f[q]);
        h[q] = __bfloat16_as_ushort(hb);
        l[q] = __bfloat16_as_ushort(__float2bfloat16_rn(f[q] - __bfloat162float(hb)));
    }
}

__global__ void k_split3(const float* __restrict__ x0, uint16_t* h0, uint16_t* l0, int n0,
                         const float* __restrict__ x1, uint16_t* h1, uint16_t* l1, int n1,
                         const float* __restrict__ x2, uint16_t* h2, uint16_t* l2, int n2) {
    int i = blockIdx.x * blockDim.x + threadIdx.x;
    const float* x; uint16_t* hh; uint16_t* ll; int j = i;
    if (j < n0) { x = x0; hh = h0; ll = l0; }
    else {
        j -= n0;
        if (j < n1) { x = x1; hh = h1; ll = l1; }
        else {
            j -= n1;
            if (j >= n2) return;
            x = x2; hh = h2; ll = l2;
        }
    }
    float4 v = ((const float4*)x)[j];
    float f[4] = {v.x, v.y, v.z, v.w};
    uint16_t h[4], l[4];
    split4(f, h, l);
    ((uint2*)hh)[j] = make_uint2(pack2(h[0], h[1]), pack2(h[2], h[3]));
    ((uint2*)ll)[j] = make_uint2(pack2(l[0], l[1]), pack2(l[2], l[3]));
}

// ---------------- tensor-core GEMM core (cp.async 3-stage, dynamic smem) ----------------
#define SA 40
#define SB 136
#define AH_SZ (128 * SA)
#define BH_SZ (32 * SB)
#define STAGE_U16 (2 * AH_SZ + 2 * BH_SZ)
#define OFF_AH 0
#define OFF_AL AH_SZ
#define OFF_BH (2 * AH_SZ)
#define OFF_BL (2 * AH_SZ + BH_SZ)
#define GEMM_SMEM_BYTES (3 * STAGE_U16 * 2)

__device__ __forceinline__ void ldsm_x4(uint32_t* r, uint32_t a) {
    asm volatile("ldmatrix.sync.aligned.m8n8.x4.shared.b16 {%0,%1,%2,%3}, [%4];"
                 : "=r"(r[0]), "=r"(r[1]), "=r"(r[2]), "=r"(r[3]) : "r"(a));
}
__device__ __forceinline__ void ldsm_x4_t(uint32_t* r, uint32_t a) {
    asm volatile("ldmatrix.sync.aligned.m8n8.x4.trans.shared.b16 {%0,%1,%2,%3}, [%4];"
                 : "=r"(r[0]), "=r"(r[1]), "=r"(r[2]), "=r"(r[3]) : "r"(a));
}
__device__ __forceinline__ void mma16816(float* c, const uint32_t* a, const uint32_t* b) {
    asm volatile("mma.sync.aligned.m16n8k16.row.col.f32.bf16.bf16.f32 "
                 "{%0,%1,%2,%3},{%4,%5,%6,%7},{%8,%9},{%0,%1,%2,%3};"
                 : "+f"(c[0]), "+f"(c[1]), "+f"(c[2]), "+f"(c[3])
                 : "r"(a[0]), "r"(a[1]), "r"(a[2]), "r"(a[3]), "r"(b[0]), "r"(b[1]));
}
__device__ __forceinline__ void cpa16(uint32_t d, const void* s, int sz) {
    asm volatile("cp.async.cg.shared.global [%0], [%1], 16, %2;"
                 :: "r"(d), "l"(s), "r"(sz));
}
__device__ __forceinline__ void cpa_commit() {
    asm volatile("cp.async.commit_group;");
}

// mainloop shared by all GEMM variants; returns accumulators by ref
struct GemmCtx {
    int ar[2], ac[2], br_[2], bc_[2];
    int asrc[2], asz[2];
};

__device__ __forceinline__ void gemm_mainloop(
    const uint16_t* __restrict__ Ah, const uint16_t* __restrict__ Al,
    const uint16_t* __restrict__ Bh, const uint16_t* __restrict__ Bl,
    int K, int Nc, int bcol, GemmCtx& cx, float acc[4][4][4],
    int lane, int wm, int wn)
{
    extern __shared__ __align__(16) uint16_t smem[];
    int ktiles = K / 32;

    auto issue_tile = [&](int kt, int buf) {
        uint16_t* stg = smem + buf * STAGE_U16;
        int k0 = kt * 32;
#pragma unroll
        for (int i = 0; i < 2; i++) {
            size_t goff = (size_t)cx.asrc[i] * K + k0 + cx.ac[i];
            uint32_t soff = cx.ar[i] * SA + cx.ac[i];
            cpa16((uint32_t)__cvta_generic_to_shared(stg + OFF_AH + soff), Ah + goff, cx.asz[i]);
            cpa16((uint32_t)__cvta_generic_to_shared(stg + OFF_AL + soff), Al + goff, cx.asz[i]);
        }
#pragma unroll
        for (int i = 0; i < 2; i++) {
            size_t goff = (size_t)(k0 + cx.br_[i]) * Nc + bcol + cx.bc_[i];
            uint32_t soff = cx.br_[i] * SB + cx.bc_[i];
            cpa16((uint32_t)__cvta_generic_to_shared(stg + OFF_BH + soff), Bh + goff, 16);
            cpa16((uint32_t)__cvta_generic_to_shared(stg + OFF_BL + soff), Bl + goff, 16);
        }
        cpa_commit();
    };

    issue_tile(0, 0);
    if (ktiles > 1) issue_tile(1, 1);

    for (int kt = 0; kt < ktiles; kt++) {
        if (kt + 1 < ktiles) {
            asm volatile("cp.async.wait_group 1;");
        } else {
            asm volatile("cp.async.wait_group 0;");
        }
        __syncthreads();
        if (kt + 2 < ktiles) issue_tile(kt + 2, (kt + 2) % 3);

        const uint16_t* stg = smem + (kt % 3) * STAGE_U16;
        const uint16_t* bAh = stg + OFF_AH;
        const uint16_t* bAl = stg + OFF_AL;
        const uint16_t* bBh = stg + OFF_BH;
        const uint16_t* bBl = stg + OFF_BL;

#pragma unroll
        for (int ks = 0; ks < 2; ks++) {
            int kk = ks * 16;
            uint32_t ah[4][4], al[4][4], bh[2][4], bl[2][4];
#pragma unroll
            for (int mt = 0; mt < 4; mt++) {
                int r = wm + mt * 16 + (lane & 15);
                int c = kk + 8 * (lane >> 4);
                ldsm_x4(ah[mt], (uint32_t)__cvta_generic_to_shared(&bAh[r * SA + c]));
                ldsm_x4(al[mt], (uint32_t)__cvta_generic_to_shared(&bAl[r * SA + c]));
            }
#pragma unroll
            for (int g = 0; g < 2; g++) {
                int r = kk + (lane & 7) + 8 * ((lane >> 3) & 1);
                int c = wn + g * 16 + 8 * (lane >> 4);
                ldsm_x4_t(bh[g], (uint32_t)__cvta_generic_to_shared(&bBh[r * SB + c]));
                ldsm_x4_t(bl[g], (uint32_t)__cvta_generic_to_shared(&bBl[r * SB + c]));
            }
#pragma unroll
            for (int mt = 0; mt < 4; mt++)
#pragma unroll
                for (int g = 0; g < 2; g++)
#pragma unroll
                    for (int hh = 0; hh < 2; hh++)
                        mma16816(acc[mt][g * 2 + hh], ah[mt], &bh[g][hh * 2]);
#pragma unroll
            for (int mt = 0; mt < 4; mt++)
#pragma unroll
                for (int g = 0; g < 2; g++)
#pragma unroll
                    for (int hh = 0; hh < 2; hh++)
                        mma16816(acc[mt][g * 2 + hh], ah[mt], &bl[g][hh * 2]);
#pragma unroll
            for (int mt = 0; mt < 4; mt++)
#pragma unroll
                for (int g = 0; g < 2; g++)
#pragma unroll
                    for (int hh = 0; hh < 2; hh++)
                        mma16816(acc[mt][g * 2 + hh], al[mt], &bh[g][hh * 2]);
        }
    }
}

// merged RGCN layer GEMM:
//   z in [0, NR): T[z-compact rows] = A[g_rows] @ Wr[z], fp16 out
//   z == NR:     hn = A @ Wl + b, fp32 out
__global__ void __launch_bounds__(256) k_gemm_rgcn(
    const uint16_t* __restrict__ Ah, const uint16_t* __restrict__ Al,
    const uint16_t* __restrict__ Wrh, const uint16_t* __restrict__ Wrl,
    const uint16_t* __restrict__ Wlh, const uint16_t* __restrict__ Wll,
    const float* __restrict__ bias, float* __restrict__ hn,
    int K, int Nc)
{
    int z = blockIdx.z;
    bool isT = (z < NR);
    int brow = blockIdx.y * 128;
    int bcol = blockIdx.x * 128;
    int base = 0, cnt = NN;
    const uint16_t *Bh, *Bl;
    if (isT) {
        base = g_cid[z * NN];
        cnt = g_cid[(z + 1) * NN] - base;
        if (brow >= cnt) return;
        Bh = Wrh + (size_t)z * K * Nc;
        Bl = Wrl + (size_t)z * K * Nc;
    } else {
        Bh = Wlh; Bl = Wll;
    }

    int tid = threadIdx.x, lane = tid & 31, wid = tid >> 5;
    int wm = (wid >> 2) * 64;
    int wn = (wid & 3) * 32;

    GemmCtx cx;
#pragma unroll
    for (int i = 0; i < 2; i++) {
        int id = tid + i * 256;
        cx.ar[i] = id >> 2; cx.ac[i] = (id & 3) * 8;
        cx.br_[i] = id >> 4; cx.bc_[i] = (id & 15) * 8;
        int rl = brow + cx.ar[i];
        if (rl < cnt) {
            cx.asrc[i] = isT ? g_rows[base + rl] : rl;
            cx.asz[i] = 16;
        } else { cx.asrc[i] = 0; cx.asz[i] = 0; }
    }

    float acc[4][4][4];
#pragma unroll
    for (int i = 0; i < 4; i++)
#pragma unroll
        for (int j = 0; j < 4; j++)
#pragma unroll
            for (int q = 0; q < 4; q++) acc[i][j][q] = 0.f;

    gemm_mainloop(Ah, Al, Bh, Bl, K, Nc, bcol, cx, acc, lane, wm, wn);

#pragma unroll
    for (int mt = 0; mt < 4; mt++) {
        int rl0 = brow + wm + mt * 16 + (lane >> 2);
        int rl1 = rl0 + 8;
#pragma unroll
        for (int nt = 0; nt < 4; nt++) {
            int c0 = bcol + wn + nt * 8 + 2 * (lane & 3);
            float v0 = acc[mt][nt][0], v1 = acc[mt][nt][1];
            float v2 = acc[mt][nt][2], v3 = acc[mt][nt][3];
            if (isT) {
                __half* Tp = g_T;
                if (rl0 < cnt)
                    *(__half2*)(Tp + (size_t)(base + rl0) * Nc + c0) = __floats2half2_rn(v0, v1);
                if (rl1 < cnt)
                    *(__half2*)(Tp + (size_t)(base + rl1) * Nc + c0) = __floats2half2_rn(v2, v3);
            } else {
                float b0 = bias[c0], b1 = bias[c0 + 1];
                if (rl0 < cnt)
                    *(float2*)(hn + (size_t)rl0 * Nc + c0) = make_float2(v0 + b0, v1 + b1);
                if (rl1 < cnt)
                    *(float2*)(hn + (size_t)rl1 * Nc + c0) = make_float2(v2 + b0, v3 + b1);
            }
        }
    }
}

// dense fp32-out GEMM (MLP head)
__global__ void __launch_bounds__(256) k_gemm_tc(
    const uint16_t* __restrict__ Ah, const uint16_t* __restrict__ Al,
    const uint16_t* __restrict__ Bh, const uint16_t* __restrict__ Bl,
    const float* __restrict__ bias, float* __restrict__ C,
    int M, int K, int Nc, int relu)
{
    int brow = blockIdx.y * 128;
    int bcol = blockIdx.x * 128;
    int tid = threadIdx.x, lane = tid & 31, wid = tid >> 5;
    int wm = (wid >> 2) * 64;
    int wn = (wid & 3) * 32;

    GemmCtx cx;
#pragma unroll
    for (int i = 0; i < 2; i++) {
        int id = tid + i * 256;
        cx.ar[i] = id >> 2; cx.ac[i] = (id & 3) * 8;
        cx.br_[i] = id >> 4; cx.bc_[i] = (id & 15) * 8;
        int rl = brow + cx.ar[i];
        if (rl < M) { cx.asrc[i] = rl; cx.asz[i] = 16; }
        else        { cx.asrc[i] = 0; cx.asz[i] = 0; }
    }

    float acc[4][4][4];
#pragma unroll
    for (int i = 0; i < 4; i++)
#pragma unroll
        for (int j = 0; j < 4; j++)
#pragma unroll
            for (int q = 0; q < 4; q++) acc[i][j][q] = 0.f;

    gemm_mainloop(Ah, Al, Bh, Bl, K, Nc, bcol, cx, acc, lane, wm, wn);

#pragma unroll
    for (int mt = 0; mt < 4; mt++) {
        int rl0 = brow + wm + mt * 16 + (lane >> 2);
        int rl1 = rl0 + 8;
#pragma unroll
        for (int nt = 0; nt < 4; nt++) {
            int c0 = bcol + wn + nt * 8 + 2 * (lane & 3);
            float b0 = bias ? bias[c0] : 0.f, b1 = bias ? bias[c0 + 1] : 0.f;
            float v0 = acc[mt][nt][0] + b0, v1 = acc[mt][nt][1] + b1;
            float v2 = acc[mt][nt][2] + b0, v3 = acc[mt][nt][3] + b1;
            if (relu) {
                v0 = fmaxf(v0, 0.f); v1 = fmaxf(v1, 0.f);
                v2 = fmaxf(v2, 0.f); v3 = fmaxf(v3, 0.f);
            }
            if (rl0 < M) *(float2*)(C + (size_t)rl0 * Nc + c0) = make_float2(v0, v1);
            if (rl1 < M) *(float2*)(C + (size_t)rl1 * Nc + c0) = make_float2(v2, v3);
        }
    }
}

// ---------------- aggregation (CSR, no atomics) + relu; T is fp16 ----------------
// MODE 0: write fp32 to hn_out. MODE 1: write bf16 hi/lo split to oh/ol.
template <int DOUT, int MODE>
__global__ void __launch_bounds__(256) k_aggregate(const float* __restrict__ hn_in,
                                                   float* __restrict__ hn_out,
                                                   uint16_t* __restrict__ oh,
                                                   uint16_t* __restrict__ ol) {
    constexpr int LANES = DOUT / 4;
    constexpr int NPB = 256 / LANES;
    int n = blockIdx.x * NPB + threadIdx.x / LANES;
    if (n >= NN) return;
    int c = (threadIdx.x % LANES) * 4;
    int beg = g_rowptr[n], end = g_rowptr[n + 1];
    size_t off = (size_t)n * DOUT + c;
    float4 acc = __ldg((const float4*)(hn_in + off));
    const __half* Tb = g_T + c;
#pragma unroll 4
    for (int e = beg; e < end; e++) {
        int p = g_epack[e];
        uint2 raw = __ldg((const uint2*)(Tb + (size_t)p * DOUT));
        __half2 p01 = *(__half2*)&raw.x;
        __half2 p23 = *(__half2*)&raw.y;
        float2 f01 = __half22float2(p01);
        float2 f23 = __half22float2(p23);
        acc.x += f01.x; acc.y += f01.y; acc.z += f23.x; acc.w += f23.y;
    }
    acc.x = fmaxf(acc.x, 0.f); acc.y = fmaxf(acc.y, 0.f);
    acc.z = fmaxf(acc.z, 0.f); acc.w = fmaxf(acc.w, 0.f);
    if (MODE == 0) {
        *(float4*)(hn_out + off) = acc;
    } else {
        float f[4] = {acc.x, acc.y, acc.z, acc.w};
        uint16_t h[4], l[4];
        split4(f, h, l);
        ((uint2*)oh)[off / 4] = make_uint2(pack2(h[0], h[1]), pack2(h[2], h[3]));
        ((uint2*)ol)[off / 4] = make_uint2(pack2(l[0], l[1]), pack2(l[2], l[3]));
    }
}

// ---------------- graph mean pooling ----------------
__global__ void k_pool(const int* __restrict__ gid, const float* __restrict__ h) {
    int n = blockIdx.x;
    int c = threadIdx.x;
    int g = gid[n];
    atomicAdd(&g_pool[g * 128 + c], h[(size_t)n * 128 + c]);
    if (c == 0) atomicAdd(&g_cnt[g], 1.0f);
}

__global__ void k_hg() {
    int g = blockIdx.x, c = threadIdx.x;
    g_hgA[g * 128 + c] = g_pool[g * 128 + c] / fmaxf(g_cnt[g], 1.0f);
}

// ---------------- classifier + softmax ----------------
__global__ void k_classifier(const float* __restrict__ hg, const float* __restrict__ Wc,
                             const float* __restrict__ bc, float* __restrict__ out) {
    int g = threadIdx.x;
    float logit[8];
#pragma unroll
    for (int c = 0; c < 8; c++) logit[c] = bc[c];
    const float* hr = hg + g * 128;
    for (int k = 0; k < 128; k++) {
        float hv = hr[k];
#pragma unroll
        for (int c = 0; c < 8; c++) logit[c] += hv * Wc[k * 8 + c];
    }
    float mx = logit[0];
#pragma unroll
    for (int c = 1; c < 8; c++) mx = fmaxf(mx, logit[c]);
    float s = 0.f;
#pragma unroll
    for (int c = 0; c < 8; c++) { logit[c] = expf(logit[c] - mx); s += logit[c]; }
    float inv = 1.f / s;
#pragma unroll
    for (int c = 0; c < 8; c++) out[g * 8 + c] = logit[c] * inv;
}

// ---------------- launch ----------------
extern "C" void kernel_launch(void* const* d_in, const int* in_sizes, int n_in,
                              void* d_out, int out_size) {
    const float* h  = (const float*)d_in[0];
    const int* src  = (const int*)d_in[1];
    const int* dst  = (const int*)d_in[2];
    const int* rel  = (const int*)d_in[3];
    const int* gid  = (const int*)d_in[4];
    const float* Wr[3] = {(const float*)d_in[5],  (const float*)d_in[8],  (const float*)d_in[11]};
    const float* Wl[3] = {(const float*)d_in[6],  (const float*)d_in[9],  (const float*)d_in[12]};
    const float* bb[3] = {(const float*)d_in[7],  (const float*)d_in[10], (const float*)d_in[13]};
    const float* Wh[3] = {(const float*)d_in[14], (const float*)d_in[16], (const float*)d_in[18]};
    const float* bh[3] = {(const float*)d_in[15], (const float*)d_in[17], (const float*)d_in[19]};
    const float* Wc = (const float*)d_in[20];
    const float* bc = (const float*)d_in[21];
    float* out = (float*)d_out;

    float *pHA, *pHB, *pHGA, *pHGB;
    cudaGetSymbolAddress((void**)&pHA, g_hA);
    cudaGetSymbolAddress((void**)&pHB, g_hB);
    cudaGetSymbolAddress((void**)&pHGA, g_hgA);
    cudaGetSymbolAddress((void**)&pHGB, g_hgB);
    uint16_t *pAh, *pAl, *pWrh, *pWrl, *pWlh, *pWll, *pHGh, *pHGl;
    cudaGetSymbolAddress((void**)&pAh, g_Ah);
    cudaGetSymbolAddress((void**)&pAl, g_Al);
    cudaGetSymbolAddress((void**)&pWrh, g_Wrh);
    cudaGetSymbolAddress((void**)&pWrl, g_Wrl);
    cudaGetSymbolAddress((void**)&pWlh, g_Wlh);
    cudaGetSymbolAddress((void**)&pWll, g_Wll);
    cudaGetSymbolAddress((void**)&pHGh, g_hgh);
    cudaGetSymbolAddress((void**)&pHGl, g_hgl);

    static int smem_set = 0;
    if (!smem_set) {
        cudaFuncSetAttribute(k_gemm_tc, cudaFuncAttributeMaxDynamicSharedMemorySize,
                             GEMM_SMEM_BYTES);
        cudaFuncSetAttribute(k_gemm_rgcn, cudaFuncAttributeMaxDynamicSharedMemorySize,
                             GEMM_SMEM_BYTES);
        smem_set = 1;
    }

    // split h + layer-0 weights
    {
        int n0 = NN * 128 / 4, n1 = NR * 128 * 128 / 4, n2 = 128 * 128 / 4;
        k_split3<<<(n0 + n1 + n2 + 255) / 256, 256>>>(
            h, pAh, pAl, n0, Wr[0], pWrh, pWrl, n1, Wl[0], pWlh, pWll, n2);
    }
    // compaction + CSR
    k_init<<<(NRNN + 255) / 256, 256>>>();
    k_edge_prep<<<(NE + 255) / 256, 256>>>(src, dst, rel);
    k_bsum<<<NBLK, 1024>>>();
    k_bscan<<<1, 1024>>>();
    k_cid<<<NBLK, 1024>>>();
    k_scan<<<1, 1024>>>();
    k_scatter<<<(NE + 255) / 256, 256>>>(src, dst, rel);

    // layer 0: merged T-GEMM + loop-GEMM, then aggregate (emit bf16)
    {
        dim3 g(1, (NN + 127) / 128, NR + 1);
        k_gemm_rgcn<<<g, 256, GEMM_SMEM_BYTES>>>(pAh, pAl, pWrh, pWrl, pWlh, pWll,
                                                 bb[0], pHA, 128, 128);
        k_aggregate<128, 1><<<(NN + 7) / 8, 256>>>(pHA, nullptr, pAh, pAl);
    }

    // layer 1: K=128 -> Nc=256
    {
        int n1 = NR * 128 * 256 / 4, n2 = 128 * 256 / 4;
        k_split3<<<(n1 + n2 + 255) / 256, 256>>>(
            Wr[1], pWrh, pWrl, n1, Wl[1], pWlh, pWll, n2, nullptr, nullptr, nullptr, 0);
        dim3 g(2, (NN + 127) / 128, NR + 1);
        k_gemm_rgcn<<<g, 256, GEMM_SMEM_BYTES>>>(pAh, pAl, pWrh, pWrl, pWlh, pWll,
                                                 bb[1], pHA, 128, 256);
        k_aggregate<256, 1><<<(NN + 3) / 4, 256>>>(pHA, nullptr, pAh, pAl);
    }

    // layer 2: K=256 -> Nc=128 (emit fp32 for pooling)
    {
        int n1 = NR * 256 * 128 / 4, n2 = 256 * 128 / 4;
        k_split3<<<(n1 + n2 + 255) / 256, 256>>>(
            Wr[2], pWrh, pWrl, n1, Wl[2], pWlh, pWll, n2, nullptr, nullptr, nullptr, 0);
        dim3 g(1, (NN + 127) / 128, NR + 1);
        k_gemm_rgcn<<<g, 256, GEMM_SMEM_BYTES>>>(pAh, pAl, pWrh, pWrl, pWlh, pWll,
                                                 bb[2], pHB, 256, 128);
        k_aggregate<128, 0><<<(NN + 7) / 8, 256>>>(pHB, pHB, nullptr, nullptr);
    }

    // graph mean pooling
    k_pool<<<NN, 128>>>(gid, pHB);
    k_hg<<<NG, 128>>>();

    // MLP head: 128 -> 128 -> 256 -> 128 (relu)
    const int mk[3] = {128, 128, 256}, mn[3] = {128, 256, 128};
    float* hin = pHGA;
    float* hout = pHGB;
    for (int l = 0; l < 3; l++) {
        int n0 = NG * mk[l] / 4, n1 = mk[l] * mn[l] / 4;
        k_split3<<<(n0 + n1 + 255) / 256, 256>>>(
            hin, pHGh, pHGl, n0, Wh[l], pWlh, pWll, n1, nullptr, nullptr, nullptr, 0);
        dim3 g(mn[l] / 128, 1, 1);
        k_gemm_tc<<<g, 256, GEMM_SMEM_BYTES>>>(pHGh, pHGl, pWlh, pWll, bh[l], hout,
                                               NG, mk[l], mn[l], 1);
        float* t = hin; hin = hout; hout = t;
    }

    // classifier + softmax
    k_classifier<<<1, NG>>>(hin, Wc, bc, out);
}